// round 1
// baseline (speedup 1.0000x reference)
#include <cuda_runtime.h>

#define NUSERS 100000
#define NITEMS 50000
#define NN     150000
#define EMB    64
#define NE     2000000
#define NB     16384

// ---------------- scratch (device globals; no allocation allowed) ----------
__device__ float g_h1[(size_t)NN * 256];     // layer-1 features h=(x@W1), [n,4,64]
__device__ float g_out1[(size_t)NN * 256];   // layer-1 aggregated output
__device__ float g_es1[NN * 4];
__device__ float g_ed1[NN * 4];
__device__ float g_att1[(size_t)NE * 4];
__device__ float g_attsum1[NN * 4];
__device__ float g_h2[(size_t)NN * 64];      // layer-2 features
__device__ float g_out2[(size_t)NN * 64];    // layer-2 aggregated output (init = all_emb, residual fused)
__device__ float g_es2[NN];
__device__ float g_ed2[NN];
__device__ float g_att2[NE];
__device__ float g_attsum2[NN];
__device__ unsigned g_max1_u;
__device__ unsigned g_max2_u;

// ordered-uint encoding for float atomicMax (handles negatives)
__device__ __forceinline__ unsigned enc_f(float f) {
    unsigned u = __float_as_uint(f);
    return (u & 0x80000000u) ? ~u : (u | 0x80000000u);
}
__device__ __forceinline__ float dec_f(unsigned u) {
    return (u & 0x80000000u) ? __uint_as_float(u ^ 0x80000000u) : __uint_as_float(~u);
}

// ---------------- init: zero accumulators, out2 := all_emb -----------------
__global__ void k_init(const float* __restrict__ user, const float* __restrict__ item) {
    size_t i0 = (size_t)blockIdx.x * blockDim.x + threadIdx.x;
    size_t stride = (size_t)gridDim.x * blockDim.x;
    float4 z = make_float4(0.f, 0.f, 0.f, 0.f);
    float4* o1 = reinterpret_cast<float4*>(g_out1);
    for (size_t i = i0; i < (size_t)NN * 64; i += stride) o1[i] = z;   // 256 floats/row = 64 f4
    for (size_t i = i0; i < (size_t)NN * 4; i += stride) g_attsum1[i] = 0.f;
    for (size_t i = i0; i < (size_t)NN; i += stride) g_attsum2[i] = 0.f;
    float4* o2 = reinterpret_cast<float4*>(g_out2);
    const float4* uf = reinterpret_cast<const float4*>(user);
    const float4* itf = reinterpret_cast<const float4*>(item);
    for (size_t i = i0; i < (size_t)NN * 16; i += stride) {            // 64 floats/row = 16 f4
        o2[i] = (i < (size_t)NUSERS * 16) ? uf[i] : itf[i - (size_t)NUSERS * 16];
    }
    if (i0 == 0) { g_max1_u = 0x007FFFFFu; g_max2_u = 0x007FFFFFu; }   // enc(-inf)
}

// ---------------- GEMM1: h1 = all_emb @ W1, plus e_src/e_dst ---------------
// 256 threads; thread t holds column t of W1 (64 floats) in registers.
__global__ void __launch_bounds__(256) k_gemm1(
    const float* __restrict__ user, const float* __restrict__ item,
    const float* __restrict__ W1, const float* __restrict__ a1) {
    __shared__ float xs[64];
    __shared__ float red[16];
    int t = threadIdx.x;
    int h = t >> 6, f = t & 63;
    float Wreg[64];
#pragma unroll
    for (int k = 0; k < 64; k++) Wreg[k] = W1[k * 256 + t];
    float al = a1[h * 128 + f];
    float ar = a1[h * 128 + 64 + f];
    int lane = t & 31, wid = t >> 5;
    for (int row = blockIdx.x; row < NN; row += gridDim.x) {
        __syncthreads();
        if (t < 64)
            xs[t] = (row < NUSERS) ? user[(size_t)row * 64 + t]
                                   : item[(size_t)(row - NUSERS) * 64 + t];
        __syncthreads();
        float acc = 0.f;
#pragma unroll
        for (int k = 0; k < 64; k++) acc = fmaf(xs[k], Wreg[k], acc);
        g_h1[(size_t)row * 256 + t] = acc;
        float vl = acc * al, vr = acc * ar;
#pragma unroll
        for (int o = 16; o > 0; o >>= 1) {
            vl += __shfl_down_sync(0xffffffffu, vl, o);
            vr += __shfl_down_sync(0xffffffffu, vr, o);
        }
        if (lane == 0) { red[wid] = vl; red[8 + wid] = vr; }
        __syncthreads();
        if (t < 4) {
            g_es1[row * 4 + t] = red[2 * t] + red[2 * t + 1];
            g_ed1[row * 4 + t] = red[8 + 2 * t] + red[8 + 2 * t + 1];
        }
    }
}

// ---------------- attention leaky-relu + global max (layer 1) --------------
__global__ void k_att1(const int* __restrict__ ei) {
    int t = threadIdx.x, lane = t & 31, wid = t >> 5;
    __shared__ float sm[8];
    float m = -3.4e38f;
    for (int idx = blockIdx.x * 256 + t; idx < NE * 4; idx += gridDim.x * 256) {
        int e = idx >> 2, h = idx & 3;
        int s = ei[e], d = ei[NE + e];
        float v = g_es1[s * 4 + h] + g_ed1[d * 4 + h];
        v = (v > 0.f) ? v : 0.2f * v;
        g_att1[idx] = v;
        m = fmaxf(m, v);
    }
#pragma unroll
    for (int o = 16; o > 0; o >>= 1) m = fmaxf(m, __shfl_down_sync(0xffffffffu, m, o));
    if (lane == 0) sm[wid] = m;
    __syncthreads();
    if (t == 0) {
        float mm = sm[0];
#pragma unroll
        for (int j = 1; j < 8; j++) mm = fmaxf(mm, sm[j]);
        atomicMax(&g_max1_u, enc_f(mm));
    }
}

// ---------------- exp + segment-sum of attention (layer 1) -----------------
__global__ void k_attexp1(const int* __restrict__ ei) {
    float M = dec_f(g_max1_u);
    for (int idx = blockIdx.x * 256 + threadIdx.x; idx < NE * 4; idx += gridDim.x * 256) {
        int e = idx >> 2, h = idx & 3;
        int d = ei[NE + e];
        float a = expf(g_att1[idx] - M);
        g_att1[idx] = a;
        atomicAdd(&g_attsum1[d * 4 + h], a);
    }
}

// ---------------- message passing layer 1 (warp per edge, 256 f) -----------
__global__ void k_msg1(const int* __restrict__ ei) {
    int gw = (blockIdx.x * blockDim.x + threadIdx.x) >> 5;
    int lane = threadIdx.x & 31;
    if (gw >= NE) return;
    int s = ei[gw], d = ei[NE + gw];
    float w = 0.f;
    if (lane < 4) w = g_att1[(size_t)gw * 4 + lane] / (g_attsum1[d * 4 + lane] + 1e-8f);
    float w0 = __shfl_sync(0xffffffffu, w, 0);
    float w1 = __shfl_sync(0xffffffffu, w, 1);
    float w2 = __shfl_sync(0xffffffffu, w, 2);
    float w3 = __shfl_sync(0xffffffffu, w, 3);
    float warr[4] = {w0, w1, w2, w3};
    size_t sb = (size_t)s * 256, db = (size_t)d * 256;
#pragma unroll
    for (int i = 0; i < 8; i++) {
        int fo = i * 32 + lane;
        float v = g_h1[sb + fo] * warr[i >> 1];
        atomicAdd(&g_out1[db + fo], v);
    }
}

// ---------------- GEMM2: h2 = elu(out1) @ W2, plus e_src/e_dst -------------
__global__ void __launch_bounds__(256) k_gemm2(
    const float* __restrict__ W2, const float* __restrict__ a2) {
    __shared__ float xs[256];
    __shared__ float red[256];
    __shared__ float red2[16];
    int t = threadIdx.x;
    int f = t & 63, ks = t >> 6;
    float Wreg[64];
#pragma unroll
    for (int kk = 0; kk < 64; kk++) Wreg[kk] = W2[(ks * 64 + kk) * 64 + f];
    float al = (t < 64) ? a2[t] : 0.f;
    float ar = (t < 64) ? a2[64 + t] : 0.f;
    int lane = t & 31, wid = t >> 5;
    for (int row = blockIdx.x; row < NN; row += gridDim.x) {
        __syncthreads();
        {
            float v = g_out1[(size_t)row * 256 + t];
            xs[t] = (v > 0.f) ? v : (expf(v) - 1.f);   // elu
        }
        __syncthreads();
        float acc = 0.f;
#pragma unroll
        for (int kk = 0; kk < 64; kk++) acc = fmaf(xs[ks * 64 + kk], Wreg[kk], acc);
        red[t] = acc;
        __syncthreads();
        if (t < 64) {
            float val = red[t] + red[64 + t] + red[128 + t] + red[192 + t];
            g_h2[(size_t)row * 64 + t] = val;
            float vl = val * al, vr = val * ar;
#pragma unroll
            for (int o = 16; o > 0; o >>= 1) {
                vl += __shfl_down_sync(0xffffffffu, vl, o);
                vr += __shfl_down_sync(0xffffffffu, vr, o);
            }
            if (lane == 0) { red2[wid] = vl; red2[8 + wid] = vr; }
        }
        __syncthreads();
        if (t == 0) {
            g_es2[row] = red2[0] + red2[1];
            g_ed2[row] = red2[8] + red2[9];
        }
    }
}

// ---------------- attention layer 2 -----------------------------------------
__global__ void k_att2(const int* __restrict__ ei) {
    int t = threadIdx.x, lane = t & 31, wid = t >> 5;
    __shared__ float sm[8];
    float m = -3.4e38f;
    for (int e = blockIdx.x * 256 + t; e < NE; e += gridDim.x * 256) {
        float v = g_es2[ei[e]] + g_ed2[ei[NE + e]];
        v = (v > 0.f) ? v : 0.2f * v;
        g_att2[e] = v;
        m = fmaxf(m, v);
    }
#pragma unroll
    for (int o = 16; o > 0; o >>= 1) m = fmaxf(m, __shfl_down_sync(0xffffffffu, m, o));
    if (lane == 0) sm[wid] = m;
    __syncthreads();
    if (t == 0) {
        float mm = sm[0];
#pragma unroll
        for (int j = 1; j < 8; j++) mm = fmaxf(mm, sm[j]);
        atomicMax(&g_max2_u, enc_f(mm));
    }
}

__global__ void k_attexp2(const int* __restrict__ ei) {
    float M = dec_f(g_max2_u);
    for (int e = blockIdx.x * 256 + threadIdx.x; e < NE; e += gridDim.x * 256) {
        int d = ei[NE + e];
        float a = expf(g_att2[e] - M);
        g_att2[e] = a;
        atomicAdd(&g_attsum2[d], a);
    }
}

// ---------------- message passing layer 2 (warp per edge, 64 f) ------------
__global__ void k_msg2(const int* __restrict__ ei) {
    int gw = (blockIdx.x * blockDim.x + threadIdx.x) >> 5;
    int lane = threadIdx.x & 31;
    if (gw >= NE) return;
    int s = ei[gw], d = ei[NE + gw];
    float w = g_att2[gw] / (g_attsum2[d] + 1e-8f);
    size_t sb = (size_t)s * 64, db = (size_t)d * 64;
#pragma unroll
    for (int i = 0; i < 2; i++) {
        int fo = i * 32 + lane;
        atomicAdd(&g_out2[db + fo], g_h2[sb + fo] * w);
    }
}

// ---------------- final scoring --------------------------------------------
__global__ void k_final(const int* __restrict__ uid, const int* __restrict__ iid,
                        float* __restrict__ out) {
    int gw = (blockIdx.x * blockDim.x + threadIdx.x) >> 5;
    int lane = threadIdx.x & 31;
    if (gw >= NB) return;
    int u = uid[gw];
    int it = NUSERS + iid[gw];
    float p = 0.f;
#pragma unroll
    for (int i = 0; i < 2; i++) {
        int f = i * 32 + lane;
        p += g_out2[(size_t)u * 64 + f] * g_out2[(size_t)it * 64 + f];
    }
#pragma unroll
    for (int o = 16; o > 0; o >>= 1) p += __shfl_down_sync(0xffffffffu, p, o);
    if (lane == 0) out[gw] = p;
}

// ---------------- launch ----------------------------------------------------
extern "C" void kernel_launch(void* const* d_in, const int* in_sizes, int n_in,
                              void* d_out, int out_size) {
    const float* user = (const float*)d_in[0];
    const float* item = (const float*)d_in[1];
    const float* W1 = (const float*)d_in[2];
    const float* a1 = (const float*)d_in[3];
    const float* W2 = (const float*)d_in[4];
    const float* a2 = (const float*)d_in[5];
    const int* ei = (const int*)d_in[6];
    const int* uid = (const int*)d_in[7];
    const int* iid = (const int*)d_in[8];
    float* out = (float*)d_out;

    k_init<<<2048, 256>>>(user, item);
    k_gemm1<<<1184, 256>>>(user, item, W1, a1);
    k_att1<<<2048, 256>>>(ei);
    k_attexp1<<<2048, 256>>>(ei);
    k_msg1<<<NE * 32 / 256, 256>>>(ei);
    k_gemm2<<<1184, 256>>>(W2, a2);
    k_att2<<<2048, 256>>>(ei);
    k_attexp2<<<2048, 256>>>(ei);
    k_msg2<<<NE * 32 / 256, 256>>>(ei);
    k_final<<<NB * 32 / 256, 256>>>(uid, iid, out);
}

// round 2
// speedup vs baseline: 1.8582x; 1.8582x over previous
#include <cuda_runtime.h>

#define NUSERS 100000
#define NITEMS 50000
#define NN     150000
#define EMB    64
#define NE     2000000
#define NB     16384
#define NBLK_SCAN 147   // ceil(NN/1024)

// ---------------- scratch (device globals) ----------------------------------
__device__ float g_h1[(size_t)NN * 256];     // layer-1 features h=(x@W1), [n,4,64]
__device__ float g_out1e[(size_t)NN * 256];  // elu(layer-1 aggregated output)
__device__ float g_es1[NN * 4];
__device__ float g_ed1[NN * 4];
__device__ float g_h2[(size_t)NN * 64];      // layer-2 features
__device__ float g_out2[(size_t)NN * 64];    // layer-2 agg + residual
__device__ float g_es2[NN];
__device__ float g_ed2[NN];
__device__ unsigned g_max1_u;
__device__ unsigned g_max2_u;

// CSR by dst
__device__ int g_cnt[NN];
__device__ int g_off[NN];
__device__ int g_cur[NN];
__device__ int g_csr_src[NE];
__device__ int g_bsum[NBLK_SCAN];
__device__ int g_btop[NBLK_SCAN];

// ordered-uint encoding for float atomicMax (handles negatives)
__device__ __forceinline__ unsigned enc_f(float f) {
    unsigned u = __float_as_uint(f);
    return (u & 0x80000000u) ? ~u : (u | 0x80000000u);
}
__device__ __forceinline__ float dec_f(unsigned u) {
    return (u & 0x80000000u) ? __uint_as_float(u ^ 0x80000000u) : __uint_as_float(~u);
}

// ---------------- init: zero histogram, reset maxes -------------------------
__global__ void k_init() {
    int i = blockIdx.x * blockDim.x + threadIdx.x;
    if (i < NN) g_cnt[i] = 0;
    if (i == 0) { g_max1_u = 0x007FFFFFu; g_max2_u = 0x007FFFFFu; }
}

// ---------------- histogram of dst -------------------------------------------
__global__ void k_hist(const int* __restrict__ ei) {
    for (int e = blockIdx.x * 256 + threadIdx.x; e < NE; e += gridDim.x * 256)
        atomicAdd(&g_cnt[ei[NE + e]], 1);
}

// ---------------- block-level scan -------------------------------------------
__global__ void __launch_bounds__(1024) k_scan_block() {
    __shared__ int sh[1024];
    int t = threadIdx.x;
    int i = blockIdx.x * 1024 + t;
    int v = (i < NN) ? g_cnt[i] : 0;
    sh[t] = v;
    __syncthreads();
#pragma unroll
    for (int o = 1; o < 1024; o <<= 1) {
        int x = (t >= o) ? sh[t - o] : 0;
        __syncthreads();
        sh[t] += x;
        __syncthreads();
    }
    if (i < NN) g_off[i] = sh[t] - v;          // exclusive within block
    if (t == 1023) g_bsum[blockIdx.x] = sh[1023];
}

__global__ void __launch_bounds__(256) k_scan_top() {
    __shared__ int sh[256];
    int t = threadIdx.x;
    int v = (t < NBLK_SCAN) ? g_bsum[t] : 0;
    sh[t] = v;
    __syncthreads();
#pragma unroll
    for (int o = 1; o < 256; o <<= 1) {
        int x = (t >= o) ? sh[t - o] : 0;
        __syncthreads();
        sh[t] += x;
        __syncthreads();
    }
    if (t < NBLK_SCAN) g_btop[t] = sh[t] - v;  // exclusive
}

__global__ void k_scan_add() {
    int i = blockIdx.x * blockDim.x + threadIdx.x;
    if (i < NN) {
        int o = g_off[i] + g_btop[i >> 10];
        g_off[i] = o;
        g_cur[i] = o;
    }
}

// ---------------- scatter edges into CSR -------------------------------------
__global__ void k_scatter(const int* __restrict__ ei) {
    int e = blockIdx.x * 256 + threadIdx.x;
    if (e >= NE) return;
    int d = ei[NE + e];
    int pos = atomicAdd(&g_cur[d], 1);
    g_csr_src[pos] = ei[e];
}

// ---------------- GEMM1: h1 = all_emb @ W1, plus e_src/e_dst -----------------
__global__ void __launch_bounds__(256) k_gemm1(
    const float* __restrict__ user, const float* __restrict__ item,
    const float* __restrict__ W1, const float* __restrict__ a1) {
    __shared__ float xs[64];
    __shared__ float red[16];
    int t = threadIdx.x;
    int h = t >> 6, f = t & 63;
    float Wreg[64];
#pragma unroll
    for (int k = 0; k < 64; k++) Wreg[k] = W1[k * 256 + t];
    float al = a1[h * 128 + f];
    float ar = a1[h * 128 + 64 + f];
    int lane = t & 31, wid = t >> 5;
    for (int row = blockIdx.x; row < NN; row += gridDim.x) {
        __syncthreads();
        if (t < 64)
            xs[t] = (row < NUSERS) ? user[(size_t)row * 64 + t]
                                   : item[(size_t)(row - NUSERS) * 64 + t];
        __syncthreads();
        float acc = 0.f;
#pragma unroll
        for (int k = 0; k < 64; k++) acc = fmaf(xs[k], Wreg[k], acc);
        g_h1[(size_t)row * 256 + t] = acc;
        float vl = acc * al, vr = acc * ar;
#pragma unroll
        for (int o = 16; o > 0; o >>= 1) {
            vl += __shfl_down_sync(0xffffffffu, vl, o);
            vr += __shfl_down_sync(0xffffffffu, vr, o);
        }
        if (lane == 0) { red[wid] = vl; red[8 + wid] = vr; }
        __syncthreads();
        if (t < 4) {
            g_es1[row * 4 + t] = red[2 * t] + red[2 * t + 1];
            g_ed1[row * 4 + t] = red[8 + 2 * t] + red[8 + 2 * t + 1];
        }
    }
}

// ---------------- global max of leaky-relu attention (layer 1) ---------------
__global__ void k_max1(const int* __restrict__ ei) {
    int t = threadIdx.x, lane = t & 31, wid = t >> 5;
    __shared__ float sm[8];
    float m = -3.4e38f;
    for (int e = blockIdx.x * 256 + t; e < NE; e += gridDim.x * 256) {
        int s = ei[e], d = ei[NE + e];
        float4 es = *reinterpret_cast<const float4*>(&g_es1[s * 4]);
        float4 ed = *reinterpret_cast<const float4*>(&g_ed1[d * 4]);
        float v0 = es.x + ed.x, v1 = es.y + ed.y, v2 = es.z + ed.z, v3 = es.w + ed.w;
        v0 = (v0 > 0.f) ? v0 : 0.2f * v0;
        v1 = (v1 > 0.f) ? v1 : 0.2f * v1;
        v2 = (v2 > 0.f) ? v2 : 0.2f * v2;
        v3 = (v3 > 0.f) ? v3 : 0.2f * v3;
        m = fmaxf(m, fmaxf(fmaxf(v0, v1), fmaxf(v2, v3)));
    }
#pragma unroll
    for (int o = 16; o > 0; o >>= 1) m = fmaxf(m, __shfl_down_sync(0xffffffffu, m, o));
    if (lane == 0) sm[wid] = m;
    __syncthreads();
    if (t == 0) {
        float mm = sm[0];
#pragma unroll
        for (int j = 1; j < 8; j++) mm = fmaxf(mm, sm[j]);
        atomicMax(&g_max1_u, enc_f(mm));
    }
}

// ---------------- layer-1 aggregation: warp per dst, fused softmax+elu -------
__global__ void __launch_bounds__(256) k_agg1() {
    int gw = (blockIdx.x * 256 + threadIdx.x) >> 5;   // dst node
    int lane = threadIdx.x & 31;
    if (gw >= NN) return;
    int d = gw;
    int n0 = g_off[d];
    int cnt = g_cnt[d];
    float M = dec_f(g_max1_u);
    float4 accA = make_float4(0.f, 0.f, 0.f, 0.f);
    float4 accB = make_float4(0.f, 0.f, 0.f, 0.f);
    float ss = 0.f;                                   // att-sum for this lane's head
    int myh = lane >> 3;                              // 8 lanes per head, lane owns feats lane*8..lane*8+7
    for (int j = n0; j < n0 + cnt; j++) {
        int s = g_csr_src[j];                          // broadcast load
        float a = 0.f;
        if (lane < 4) {
            float v = g_es1[s * 4 + lane] + g_ed1[d * 4 + lane];
            v = (v > 0.f) ? v : 0.2f * v;
            a = __expf(v - M);
        }
        float my_a = __shfl_sync(0xffffffffu, a, myh);
        ss += my_a;
        const float4* hrow = reinterpret_cast<const float4*>(&g_h1[(size_t)s * 256 + lane * 8]);
        float4 ha = hrow[0], hb = hrow[1];
        accA.x = fmaf(my_a, ha.x, accA.x); accA.y = fmaf(my_a, ha.y, accA.y);
        accA.z = fmaf(my_a, ha.z, accA.z); accA.w = fmaf(my_a, ha.w, accA.w);
        accB.x = fmaf(my_a, hb.x, accB.x); accB.y = fmaf(my_a, hb.y, accB.y);
        accB.z = fmaf(my_a, hb.z, accB.z); accB.w = fmaf(my_a, hb.w, accB.w);
    }
    float inv = 1.f / (ss + 1e-8f);
    float o[8] = {accA.x * inv, accA.y * inv, accA.z * inv, accA.w * inv,
                  accB.x * inv, accB.y * inv, accB.z * inv, accB.w * inv};
#pragma unroll
    for (int k = 0; k < 8; k++) o[k] = (o[k] > 0.f) ? o[k] : expm1f(o[k]);   // fused elu
    float4* dst = reinterpret_cast<float4*>(&g_out1e[(size_t)d * 256 + lane * 8]);
    dst[0] = make_float4(o[0], o[1], o[2], o[3]);
    dst[1] = make_float4(o[4], o[5], o[6], o[7]);
}

// ---------------- GEMM2: h2 = out1e @ W2, plus e_src/e_dst -------------------
__global__ void __launch_bounds__(256) k_gemm2(
    const float* __restrict__ W2, const float* __restrict__ a2) {
    __shared__ float xs[256];
    __shared__ float red[256];
    __shared__ float red2[16];
    int t = threadIdx.x;
    int f = t & 63, ks = t >> 6;
    float Wreg[64];
#pragma unroll
    for (int kk = 0; kk < 64; kk++) Wreg[kk] = W2[(ks * 64 + kk) * 64 + f];
    float al = (t < 64) ? a2[t] : 0.f;
    float ar = (t < 64) ? a2[64 + t] : 0.f;
    int lane = t & 31, wid = t >> 5;
    for (int row = blockIdx.x; row < NN; row += gridDim.x) {
        __syncthreads();
        xs[t] = g_out1e[(size_t)row * 256 + t];
        __syncthreads();
        float acc = 0.f;
#pragma unroll
        for (int kk = 0; kk < 64; kk++) acc = fmaf(xs[ks * 64 + kk], Wreg[kk], acc);
        red[t] = acc;
        __syncthreads();
        if (t < 64) {
            float val = red[t] + red[64 + t] + red[128 + t] + red[192 + t];
            g_h2[(size_t)row * 64 + t] = val;
            float vl = val * al, vr = val * ar;
#pragma unroll
            for (int o = 16; o > 0; o >>= 1) {
                vl += __shfl_down_sync(0xffffffffu, vl, o);
                vr += __shfl_down_sync(0xffffffffu, vr, o);
            }
            if (lane == 0) { red2[wid] = vl; red2[8 + wid] = vr; }
        }
        __syncthreads();
        if (t == 0) {
            g_es2[row] = red2[0] + red2[1];
            g_ed2[row] = red2[8] + red2[9];
        }
    }
}

// ---------------- global max (layer 2) ---------------------------------------
__global__ void k_max2(const int* __restrict__ ei) {
    int t = threadIdx.x, lane = t & 31, wid = t >> 5;
    __shared__ float sm[8];
    float m = -3.4e38f;
    for (int e = blockIdx.x * 256 + t; e < NE; e += gridDim.x * 256) {
        float v = g_es2[ei[e]] + g_ed2[ei[NE + e]];
        v = (v > 0.f) ? v : 0.2f * v;
        m = fmaxf(m, v);
    }
#pragma unroll
    for (int o = 16; o > 0; o >>= 1) m = fmaxf(m, __shfl_down_sync(0xffffffffu, m, o));
    if (lane == 0) sm[wid] = m;
    __syncthreads();
    if (t == 0) {
        float mm = sm[0];
#pragma unroll
        for (int j = 1; j < 8; j++) mm = fmaxf(mm, sm[j]);
        atomicMax(&g_max2_u, enc_f(mm));
    }
}

// ---------------- layer-2 aggregation: warp per dst, fused residual ----------
__global__ void __launch_bounds__(256) k_agg2(
    const float* __restrict__ user, const float* __restrict__ item) {
    int gw = (blockIdx.x * 256 + threadIdx.x) >> 5;
    int lane = threadIdx.x & 31;
    if (gw >= NN) return;
    int d = gw;
    int n0 = g_off[d];
    int cnt = g_cnt[d];
    float M = dec_f(g_max2_u);
    float2 acc = make_float2(0.f, 0.f);
    float ss = 0.f;
    float ed_d = g_ed2[d];
    for (int j = n0; j < n0 + cnt; j++) {
        int s = g_csr_src[j];
        float a = 0.f;
        if (lane == 0) {
            float v = g_es2[s] + ed_d;
            v = (v > 0.f) ? v : 0.2f * v;
            a = __expf(v - M);
        }
        a = __shfl_sync(0xffffffffu, a, 0);
        ss += a;
        float2 h = *reinterpret_cast<const float2*>(&g_h2[(size_t)s * 64 + lane * 2]);
        acc.x = fmaf(a, h.x, acc.x);
        acc.y = fmaf(a, h.y, acc.y);
    }
    float inv = 1.f / (ss + 1e-8f);
    float2 emb = (d < NUSERS)
        ? *reinterpret_cast<const float2*>(&user[(size_t)d * 64 + lane * 2])
        : *reinterpret_cast<const float2*>(&item[(size_t)(d - NUSERS) * 64 + lane * 2]);
    float2 out = make_float2(acc.x * inv + emb.x, acc.y * inv + emb.y);
    *reinterpret_cast<float2*>(&g_out2[(size_t)d * 64 + lane * 2]) = out;
}

// ---------------- final scoring ----------------------------------------------
__global__ void k_final(const int* __restrict__ uid, const int* __restrict__ iid,
                        float* __restrict__ out) {
    int gw = (blockIdx.x * blockDim.x + threadIdx.x) >> 5;
    int lane = threadIdx.x & 31;
    if (gw >= NB) return;
    int u = uid[gw];
    int it = NUSERS + iid[gw];
    float p = 0.f;
#pragma unroll
    for (int i = 0; i < 2; i++) {
        int f = i * 32 + lane;
        p += g_out2[(size_t)u * 64 + f] * g_out2[(size_t)it * 64 + f];
    }
#pragma unroll
    for (int o = 16; o > 0; o >>= 1) p += __shfl_down_sync(0xffffffffu, p, o);
    if (lane == 0) out[gw] = p;
}

// ---------------- launch -------------------------------------------------------
extern "C" void kernel_launch(void* const* d_in, const int* in_sizes, int n_in,
                              void* d_out, int out_size) {
    const float* user = (const float*)d_in[0];
    const float* item = (const float*)d_in[1];
    const float* W1 = (const float*)d_in[2];
    const float* a1 = (const float*)d_in[3];
    const float* W2 = (const float*)d_in[4];
    const float* a2 = (const float*)d_in[5];
    const int* ei = (const int*)d_in[6];
    const int* uid = (const int*)d_in[7];
    const int* iid = (const int*)d_in[8];
    float* out = (float*)d_out;

    k_init<<<(NN + 255) / 256, 256>>>();
    k_hist<<<2048, 256>>>(ei);
    k_scan_block<<<NBLK_SCAN, 1024>>>();
    k_scan_top<<<1, 256>>>();
    k_scan_add<<<(NN + 255) / 256, 256>>>();
    k_scatter<<<(NE + 255) / 256, 256>>>(ei);
    k_gemm1<<<1184, 256>>>(user, item, W1, a1);
    k_max1<<<2048, 256>>>(ei);
    k_agg1<<<(NN * 32 + 255) / 256, 256>>>();
    k_gemm2<<<1184, 256>>>(W2, a2);
    k_max2<<<2048, 256>>>(ei);
    k_agg2<<<(NN * 32 + 255) / 256, 256>>>(user, item);
    k_final<<<NB * 32 / 256, 256>>>(uid, iid, out);
}

// round 3
// speedup vs baseline: 2.0322x; 1.0936x over previous
#include <cuda_runtime.h>
#include <cuda_fp16.h>

#define NUSERS 100000
#define NITEMS 50000
#define NN     150000
#define EMB    64
#define NE     2000000
#define NB     16384
#define NBLK_SCAN 147   // ceil(NN/1024)

// ---------------- scratch (device globals) ----------------------------------
__device__ __half g_h1h[(size_t)NN * 256];   // layer-1 features fp16, [n,4,64]
__device__ float  g_out1e[(size_t)NN * 256]; // elu(layer-1 aggregated output), fp32
__device__ float  g_es1[NN * 4];
__device__ float  g_ed1[NN * 4];
__device__ __half g_h2h[(size_t)NN * 64];    // layer-2 features fp16
__device__ float  g_out2[(size_t)NN * 64];   // layer-2 agg + residual
__device__ float  g_es2[NN];
__device__ float  g_ed2[NN];
__device__ unsigned g_max1_u;
__device__ unsigned g_max2_u;

// CSR by dst
__device__ int g_cnt[NN];
__device__ int g_off[NN];
__device__ int g_cur[NN];
__device__ int g_csr_src[NE];
__device__ int g_bsum[NBLK_SCAN];
__device__ int g_btop[NBLK_SCAN];

__device__ __forceinline__ unsigned enc_f(float f) {
    unsigned u = __float_as_uint(f);
    return (u & 0x80000000u) ? ~u : (u | 0x80000000u);
}
__device__ __forceinline__ float dec_f(unsigned u) {
    return (u & 0x80000000u) ? __uint_as_float(u ^ 0x80000000u) : __uint_as_float(~u);
}

// ---------------- init ---------------------------------------------------------
__global__ void k_init() {
    int i = blockIdx.x * blockDim.x + threadIdx.x;
    if (i < NN) g_cnt[i] = 0;
    if (i == 0) { g_max1_u = 0x007FFFFFu; g_max2_u = 0x007FFFFFu; }
}

// ---------------- histogram of dst ---------------------------------------------
__global__ void k_hist(const int* __restrict__ ei) {
    for (int e = blockIdx.x * 256 + threadIdx.x; e < NE; e += gridDim.x * 256)
        atomicAdd(&g_cnt[ei[NE + e]], 1);
}

// ---------------- scans ---------------------------------------------------------
__global__ void __launch_bounds__(1024) k_scan_block() {
    __shared__ int sh[1024];
    int t = threadIdx.x;
    int i = blockIdx.x * 1024 + t;
    int v = (i < NN) ? g_cnt[i] : 0;
    sh[t] = v;
    __syncthreads();
#pragma unroll
    for (int o = 1; o < 1024; o <<= 1) {
        int x = (t >= o) ? sh[t - o] : 0;
        __syncthreads();
        sh[t] += x;
        __syncthreads();
    }
    if (i < NN) g_off[i] = sh[t] - v;
    if (t == 1023) g_bsum[blockIdx.x] = sh[1023];
}

__global__ void __launch_bounds__(256) k_scan_top() {
    __shared__ int sh[256];
    int t = threadIdx.x;
    int v = (t < NBLK_SCAN) ? g_bsum[t] : 0;
    sh[t] = v;
    __syncthreads();
#pragma unroll
    for (int o = 1; o < 256; o <<= 1) {
        int x = (t >= o) ? sh[t - o] : 0;
        __syncthreads();
        sh[t] += x;
        __syncthreads();
    }
    if (t < NBLK_SCAN) g_btop[t] = sh[t] - v;
}

__global__ void k_scan_add() {
    int i = blockIdx.x * blockDim.x + threadIdx.x;
    if (i < NN) {
        int o = g_off[i] + g_btop[i >> 10];
        g_off[i] = o;
        g_cur[i] = o;
    }
}

// ---------------- scatter edges into CSR ----------------------------------------
__global__ void k_scatter(const int* __restrict__ ei) {
    int e = blockIdx.x * 256 + threadIdx.x;
    if (e >= NE) return;
    int d = ei[NE + e];
    int pos = atomicAdd(&g_cur[d], 1);
    g_csr_src[pos] = ei[e];
}

// ---------------- GEMM1: h1 = all_emb @ W1 (store fp16), plus e_src/e_dst -------
__global__ void __launch_bounds__(256) k_gemm1(
    const float* __restrict__ user, const float* __restrict__ item,
    const float* __restrict__ W1, const float* __restrict__ a1) {
    __shared__ float xs[64];
    __shared__ float red[16];
    int t = threadIdx.x;
    int h = t >> 6, f = t & 63;
    float Wreg[64];
#pragma unroll
    for (int k = 0; k < 64; k++) Wreg[k] = W1[k * 256 + t];
    float al = a1[h * 128 + f];
    float ar = a1[h * 128 + 64 + f];
    int lane = t & 31, wid = t >> 5;
    for (int row = blockIdx.x; row < NN; row += gridDim.x) {
        __syncthreads();
        if (t < 64)
            xs[t] = (row < NUSERS) ? user[(size_t)row * 64 + t]
                                   : item[(size_t)(row - NUSERS) * 64 + t];
        __syncthreads();
        float acc = 0.f;
#pragma unroll
        for (int k = 0; k < 64; k++) acc = fmaf(xs[k], Wreg[k], acc);
        g_h1h[(size_t)row * 256 + t] = __float2half(acc);
        float vl = acc * al, vr = acc * ar;
#pragma unroll
        for (int o = 16; o > 0; o >>= 1) {
            vl += __shfl_down_sync(0xffffffffu, vl, o);
            vr += __shfl_down_sync(0xffffffffu, vr, o);
        }
        if (lane == 0) { red[wid] = vl; red[8 + wid] = vr; }
        __syncthreads();
        if (t < 4) {
            g_es1[row * 4 + t] = red[2 * t] + red[2 * t + 1];
            g_ed1[row * 4 + t] = red[8 + 2 * t] + red[8 + 2 * t + 1];
        }
    }
}

// ---------------- global max (layer 1) -------------------------------------------
__global__ void k_max1(const int* __restrict__ ei) {
    int t = threadIdx.x, lane = t & 31, wid = t >> 5;
    __shared__ float sm[8];
    float m = -3.4e38f;
    for (int e = blockIdx.x * 256 + t; e < NE; e += gridDim.x * 256) {
        int s = ei[e], d = ei[NE + e];
        float4 es = *reinterpret_cast<const float4*>(&g_es1[s * 4]);
        float4 ed = *reinterpret_cast<const float4*>(&g_ed1[d * 4]);
        float v0 = es.x + ed.x, v1 = es.y + ed.y, v2 = es.z + ed.z, v3 = es.w + ed.w;
        v0 = (v0 > 0.f) ? v0 : 0.2f * v0;
        v1 = (v1 > 0.f) ? v1 : 0.2f * v1;
        v2 = (v2 > 0.f) ? v2 : 0.2f * v2;
        v3 = (v3 > 0.f) ? v3 : 0.2f * v3;
        m = fmaxf(m, fmaxf(fmaxf(v0, v1), fmaxf(v2, v3)));
    }
#pragma unroll
    for (int o = 16; o > 0; o >>= 1) m = fmaxf(m, __shfl_down_sync(0xffffffffu, m, o));
    if (lane == 0) sm[wid] = m;
    __syncthreads();
    if (t == 0) {
        float mm = sm[0];
#pragma unroll
        for (int j = 1; j < 8; j++) mm = fmaxf(mm, sm[j]);
        atomicMax(&g_max1_u, enc_f(mm));
    }
}

// ---------------- layer-1 aggregation: warp per dst, fp16 gather ------------------
__global__ void __launch_bounds__(256) k_agg1() {
    int gw = (blockIdx.x * 256 + threadIdx.x) >> 5;
    int lane = threadIdx.x & 31;
    if (gw >= NN) return;
    int d = gw;
    int n0 = g_off[d];
    int cnt = g_cnt[d];
    float M = dec_f(g_max1_u);
    float acc[8] = {0.f, 0.f, 0.f, 0.f, 0.f, 0.f, 0.f, 0.f};
    float ss = 0.f;
    int myh = lane >> 3;                           // lane owns feats lane*8..lane*8+7 (one head)
    float ed_l = (lane < 4) ? g_ed1[d * 4 + lane] : 0.f;   // loop-invariant
    for (int j = n0; j < n0 + cnt; j++) {
        int s = g_csr_src[j];
        float a = 0.f;
        if (lane < 4) {
            float v = g_es1[s * 4 + lane] + ed_l;
            v = (v > 0.f) ? v : 0.2f * v;
            a = __expf(v - M);
        }
        float my_a = __shfl_sync(0xffffffffu, a, myh);
        ss += my_a;
        // 8 halves = 16 bytes per lane, 512B coalesced per warp
        float4 raw = *reinterpret_cast<const float4*>(&g_h1h[(size_t)s * 256 + lane * 8]);
        const __half2* hp = reinterpret_cast<const __half2*>(&raw);
#pragma unroll
        for (int q = 0; q < 4; q++) {
            float2 hf = __half22float2(hp[q]);
            acc[2 * q]     = fmaf(my_a, hf.x, acc[2 * q]);
            acc[2 * q + 1] = fmaf(my_a, hf.y, acc[2 * q + 1]);
        }
    }
    float inv = 1.f / (ss + 1e-8f);
    float o[8];
#pragma unroll
    for (int k = 0; k < 8; k++) {
        o[k] = acc[k] * inv;
        o[k] = (o[k] > 0.f) ? o[k] : expm1f(o[k]);   // fused elu
    }
    float4* dst = reinterpret_cast<float4*>(&g_out1e[(size_t)d * 256 + lane * 8]);
    dst[0] = make_float4(o[0], o[1], o[2], o[3]);
    dst[1] = make_float4(o[4], o[5], o[6], o[7]);
}

// ---------------- GEMM2: h2 = out1e @ W2 (store fp16), plus e_src/e_dst ----------
__global__ void __launch_bounds__(256) k_gemm2(
    const float* __restrict__ W2, const float* __restrict__ a2) {
    __shared__ float xs[256];
    __shared__ float red[256];
    __shared__ float red2[16];
    int t = threadIdx.x;
    int f = t & 63, ks = t >> 6;
    float Wreg[64];
#pragma unroll
    for (int kk = 0; kk < 64; kk++) Wreg[kk] = W2[(ks * 64 + kk) * 64 + f];
    float al = (t < 64) ? a2[t] : 0.f;
    float ar = (t < 64) ? a2[64 + t] : 0.f;
    int lane = t & 31, wid = t >> 5;
    for (int row = blockIdx.x; row < NN; row += gridDim.x) {
        __syncthreads();
        xs[t] = g_out1e[(size_t)row * 256 + t];
        __syncthreads();
        float acc = 0.f;
#pragma unroll
        for (int kk = 0; kk < 64; kk++) acc = fmaf(xs[ks * 64 + kk], Wreg[kk], acc);
        red[t] = acc;
        __syncthreads();
        if (t < 64) {
            float val = red[t] + red[64 + t] + red[128 + t] + red[192 + t];
            g_h2h[(size_t)row * 64 + t] = __float2half(val);
            float vl = val * al, vr = val * ar;
#pragma unroll
            for (int o = 16; o > 0; o >>= 1) {
                vl += __shfl_down_sync(0xffffffffu, vl, o);
                vr += __shfl_down_sync(0xffffffffu, vr, o);
            }
            if (lane == 0) { red2[wid] = vl; red2[8 + wid] = vr; }
        }
        __syncthreads();
        if (t == 0) {
            g_es2[row] = red2[0] + red2[1];
            g_ed2[row] = red2[8] + red2[9];
        }
    }
}

// ---------------- global max (layer 2) --------------------------------------------
__global__ void k_max2(const int* __restrict__ ei) {
    int t = threadIdx.x, lane = t & 31, wid = t >> 5;
    __shared__ float sm[8];
    float m = -3.4e38f;
    for (int e = blockIdx.x * 256 + t; e < NE; e += gridDim.x * 256) {
        float v = g_es2[ei[e]] + g_ed2[ei[NE + e]];
        v = (v > 0.f) ? v : 0.2f * v;
        m = fmaxf(m, v);
    }
#pragma unroll
    for (int o = 16; o > 0; o >>= 1) m = fmaxf(m, __shfl_down_sync(0xffffffffu, m, o));
    if (lane == 0) sm[wid] = m;
    __syncthreads();
    if (t == 0) {
        float mm = sm[0];
#pragma unroll
        for (int j = 1; j < 8; j++) mm = fmaxf(mm, sm[j]);
        atomicMax(&g_max2_u, enc_f(mm));
    }
}

// ---------------- layer-2 aggregation: warp per dst, fp16 gather, residual --------
__global__ void __launch_bounds__(256) k_agg2(
    const float* __restrict__ user, const float* __restrict__ item) {
    int gw = (blockIdx.x * 256 + threadIdx.x) >> 5;
    int lane = threadIdx.x & 31;
    if (gw >= NN) return;
    int d = gw;
    int n0 = g_off[d];
    int cnt = g_cnt[d];
    float M = dec_f(g_max2_u);
    float2 acc = make_float2(0.f, 0.f);
    float ss = 0.f;
    float ed_d = g_ed2[d];
    for (int j = n0; j < n0 + cnt; j++) {
        int s = g_csr_src[j];
        float a = 0.f;
        if (lane == 0) {
            float v = g_es2[s] + ed_d;
            v = (v > 0.f) ? v : 0.2f * v;
            a = __expf(v - M);
        }
        a = __shfl_sync(0xffffffffu, a, 0);
        ss += a;
        // 2 halves = 4 bytes per lane, 128B coalesced per warp
        float2 h = __half22float2(*reinterpret_cast<const __half2*>(&g_h2h[(size_t)s * 64 + lane * 2]));
        acc.x = fmaf(a, h.x, acc.x);
        acc.y = fmaf(a, h.y, acc.y);
    }
    float inv = 1.f / (ss + 1e-8f);
    float2 emb = (d < NUSERS)
        ? *reinterpret_cast<const float2*>(&user[(size_t)d * 64 + lane * 2])
        : *reinterpret_cast<const float2*>(&item[(size_t)(d - NUSERS) * 64 + lane * 2]);
    float2 out = make_float2(acc.x * inv + emb.x, acc.y * inv + emb.y);
    *reinterpret_cast<float2*>(&g_out2[(size_t)d * 64 + lane * 2]) = out;
}

// ---------------- final scoring -----------------------------------------------------
__global__ void k_final(const int* __restrict__ uid, const int* __restrict__ iid,
                        float* __restrict__ out) {
    int gw = (blockIdx.x * blockDim.x + threadIdx.x) >> 5;
    int lane = threadIdx.x & 31;
    if (gw >= NB) return;
    int u = uid[gw];
    int it = NUSERS + iid[gw];
    float p = 0.f;
#pragma unroll
    for (int i = 0; i < 2; i++) {
        int f = i * 32 + lane;
        p += g_out2[(size_t)u * 64 + f] * g_out2[(size_t)it * 64 + f];
    }
#pragma unroll
    for (int o = 16; o > 0; o >>= 1) p += __shfl_down_sync(0xffffffffu, p, o);
    if (lane == 0) out[gw] = p;
}

// ---------------- launch --------------------------------------------------------------
extern "C" void kernel_launch(void* const* d_in, const int* in_sizes, int n_in,
                              void* d_out, int out_size) {
    const float* user = (const float*)d_in[0];
    const float* item = (const float*)d_in[1];
    const float* W1 = (const float*)d_in[2];
    const float* a1 = (const float*)d_in[3];
    const float* W2 = (const float*)d_in[4];
    const float* a2 = (const float*)d_in[5];
    const int* ei = (const int*)d_in[6];
    const int* uid = (const int*)d_in[7];
    const int* iid = (const int*)d_in[8];
    float* out = (float*)d_out;

    k_init<<<(NN + 255) / 256, 256>>>();
    k_hist<<<2048, 256>>>(ei);
    k_scan_block<<<NBLK_SCAN, 1024>>>();
    k_scan_top<<<1, 256>>>();
    k_scan_add<<<(NN + 255) / 256, 256>>>();
    k_scatter<<<(NE + 255) / 256, 256>>>(ei);
    k_gemm1<<<1184, 256>>>(user, item, W1, a1);
    k_max1<<<2048, 256>>>(ei);
    k_agg1<<<(NN * 32 + 255) / 256, 256>>>();
    k_gemm2<<<1184, 256>>>(W2, a2);
    k_max2<<<2048, 256>>>(ei);
    k_agg2<<<(NN * 32 + 255) / 256, 256>>>(user, item);
    k_final<<<NB * 32 / 256, 256>>>(uid, iid, out);
}

// round 4
// speedup vs baseline: 3.2785x; 1.6133x over previous
#include <cuda_runtime.h>
#include <cuda_fp16.h>

#define NUSERS 100000
#define NITEMS 50000
#define NN     150000
#define EMB    64
#define NE     2000000
#define NB     16384
#define NBLK_SCAN 147   // ceil(NN/1024)

// ---------------- scratch (device globals) ----------------------------------
__device__ __half g_h1h[(size_t)NN * 256];   // layer-1 features fp16, [n,4,64]
__device__ __half g_out1eh[(size_t)NN * 256];// elu(agg1 output), fp16
__device__ float  g_es1[NN * 4];
__device__ float  g_ed1[NN * 4];
__device__ __half g_h2h[(size_t)NN * 64];    // layer-2 features fp16
__device__ float  g_out2[(size_t)NN * 64];   // layer-2 agg + residual
__device__ float  g_es2[NN];
__device__ float  g_ed2[NN];
__device__ unsigned g_maxes1_u, g_maxed1_u;  // node-wise maxes (upper bound for edge max)
__device__ unsigned g_maxes2_u, g_maxed2_u;

// CSR by dst
__device__ int g_cnt[NN];
__device__ int g_off[NN];
__device__ int g_cur[NN];
__device__ int g_csr_src[NE];
__device__ int g_bsum[NBLK_SCAN];
__device__ int g_btop[NBLK_SCAN];

__device__ __forceinline__ unsigned enc_f(float f) {
    unsigned u = __float_as_uint(f);
    return (u & 0x80000000u) ? ~u : (u | 0x80000000u);
}
__device__ __forceinline__ float dec_f(unsigned u) {
    return (u & 0x80000000u) ? __uint_as_float(u ^ 0x80000000u) : __uint_as_float(~u);
}
__device__ __forceinline__ float lrelu(float v) { return (v > 0.f) ? v : 0.2f * v; }

// ---------------- init ---------------------------------------------------------
__global__ void k_init() {
    int i = blockIdx.x * blockDim.x + threadIdx.x;
    if (i < NN) g_cnt[i] = 0;
    if (i == 0) {
        g_maxes1_u = 0x007FFFFFu; g_maxed1_u = 0x007FFFFFu;  // enc(-inf)
        g_maxes2_u = 0x007FFFFFu; g_maxed2_u = 0x007FFFFFu;
    }
}

// ---------------- histogram of dst ---------------------------------------------
__global__ void k_hist(const int* __restrict__ ei) {
    for (int e = blockIdx.x * 256 + threadIdx.x; e < NE; e += gridDim.x * 256)
        atomicAdd(&g_cnt[ei[NE + e]], 1);
}

// ---------------- scans ---------------------------------------------------------
__global__ void __launch_bounds__(1024) k_scan_block() {
    __shared__ int sh[1024];
    int t = threadIdx.x;
    int i = blockIdx.x * 1024 + t;
    int v = (i < NN) ? g_cnt[i] : 0;
    sh[t] = v;
    __syncthreads();
#pragma unroll
    for (int o = 1; o < 1024; o <<= 1) {
        int x = (t >= o) ? sh[t - o] : 0;
        __syncthreads();
        sh[t] += x;
        __syncthreads();
    }
    if (i < NN) g_off[i] = sh[t] - v;
    if (t == 1023) g_bsum[blockIdx.x] = sh[1023];
}

__global__ void __launch_bounds__(256) k_scan_top() {
    __shared__ int sh[256];
    int t = threadIdx.x;
    int v = (t < NBLK_SCAN) ? g_bsum[t] : 0;
    sh[t] = v;
    __syncthreads();
#pragma unroll
    for (int o = 1; o < 256; o <<= 1) {
        int x = (t >= o) ? sh[t - o] : 0;
        __syncthreads();
        sh[t] += x;
        __syncthreads();
    }
    if (t < NBLK_SCAN) g_btop[t] = sh[t] - v;
}

__global__ void k_scan_add() {
    int i = blockIdx.x * blockDim.x + threadIdx.x;
    if (i < NN) {
        int o = g_off[i] + g_btop[i >> 10];
        g_off[i] = o;
        g_cur[i] = o;
    }
}

// ---------------- scatter edges into CSR ----------------------------------------
__global__ void k_scatter(const int* __restrict__ ei) {
    int e = blockIdx.x * 256 + threadIdx.x;
    if (e >= NE) return;
    int d = ei[NE + e];
    int pos = atomicAdd(&g_cur[d], 1);
    g_csr_src[pos] = ei[e];
}

// ---------------- GEMM1 (4 rows/iter): h1 = all_emb @ W1, es/ed + node maxes ----
__global__ void __launch_bounds__(256) k_gemm1(
    const float* __restrict__ user, const float* __restrict__ item,
    const float* __restrict__ W1, const float* __restrict__ a1) {
    __shared__ float xs[4][64];
    __shared__ float red_l[4][8];
    __shared__ float red_r[4][8];
    int t = threadIdx.x;
    int h = t >> 6, f = t & 63;
    float Wreg[64];
#pragma unroll
    for (int k = 0; k < 64; k++) Wreg[k] = W1[k * 256 + t];
    float al = a1[h * 128 + f];
    float ar = a1[h * 128 + 64 + f];
    int lane = t & 31, wid = t >> 5;
    float mx_es = -3.4e38f, mx_ed = -3.4e38f;
    for (int row0 = blockIdx.x * 4; row0 < NN; row0 += gridDim.x * 4) {
        __syncthreads();
        {   // load 4 rows of input: thread t -> row (t>>6), feat (t&63)
            int rr = t >> 6, ff = t & 63;
            int row = row0 + rr;
            xs[rr][ff] = (row < NUSERS) ? user[(size_t)row * 64 + ff]
                                        : item[(size_t)(row - NUSERS) * 64 + ff];
        }
        __syncthreads();
        float acc[4] = {0.f, 0.f, 0.f, 0.f};
#pragma unroll
        for (int k = 0; k < 64; k++) {
            float w = Wreg[k];
            acc[0] = fmaf(xs[0][k], w, acc[0]);
            acc[1] = fmaf(xs[1][k], w, acc[1]);
            acc[2] = fmaf(xs[2][k], w, acc[2]);
            acc[3] = fmaf(xs[3][k], w, acc[3]);
        }
#pragma unroll
        for (int rr = 0; rr < 4; rr++)
            g_h1h[(size_t)(row0 + rr) * 256 + t] = __float2half(acc[rr]);
        float vl[4], vr[4];
#pragma unroll
        for (int rr = 0; rr < 4; rr++) { vl[rr] = acc[rr] * al; vr[rr] = acc[rr] * ar; }
#pragma unroll
        for (int o = 16; o > 0; o >>= 1) {
#pragma unroll
            for (int rr = 0; rr < 4; rr++) {
                vl[rr] += __shfl_down_sync(0xffffffffu, vl[rr], o);
                vr[rr] += __shfl_down_sync(0xffffffffu, vr[rr], o);
            }
        }
        if (lane == 0) {
#pragma unroll
            for (int rr = 0; rr < 4; rr++) { red_l[rr][wid] = vl[rr]; red_r[rr][wid] = vr[rr]; }
        }
        __syncthreads();
        if (t < 16) {
            int rr = t >> 2, hh = t & 3;
            float es = red_l[rr][2 * hh] + red_l[rr][2 * hh + 1];
            float ed = red_r[rr][2 * hh] + red_r[rr][2 * hh + 1];
            g_es1[(row0 + rr) * 4 + hh] = es;
            g_ed1[(row0 + rr) * 4 + hh] = ed;
            mx_es = fmaxf(mx_es, es);
            mx_ed = fmaxf(mx_ed, ed);
        }
    }
    if (t < 16) {
        atomicMax(&g_maxes1_u, enc_f(mx_es));
        atomicMax(&g_maxed1_u, enc_f(mx_ed));
    }
}

// ---------------- layer-1 aggregation: warp/dst, unroll-2, fp16, fused elu -------
__global__ void __launch_bounds__(256) k_agg1() {
    int gw = (blockIdx.x * 256 + threadIdx.x) >> 5;
    int lane = threadIdx.x & 31;
    if (gw >= NN) return;
    int d = gw;
    int n0 = g_off[d];
    int cnt = g_cnt[d];
    float M = lrelu(dec_f(g_maxes1_u) + dec_f(g_maxed1_u));   // upper bound of edge max
    float acc[8] = {0.f, 0.f, 0.f, 0.f, 0.f, 0.f, 0.f, 0.f};
    float ss = 0.f;
    int myh = lane >> 3;
    float ed_l = (lane < 4) ? g_ed1[d * 4 + lane] : 0.f;
    int j = n0, end = n0 + cnt;
    for (; j + 1 < end; j += 2) {
        int s0 = g_csr_src[j];
        int s1 = g_csr_src[j + 1];
        float4 raw0 = *reinterpret_cast<const float4*>(&g_h1h[(size_t)s0 * 256 + lane * 8]);
        float4 raw1 = *reinterpret_cast<const float4*>(&g_h1h[(size_t)s1 * 256 + lane * 8]);
        float a0 = 0.f, a1 = 0.f;
        if (lane < 4) {
            a0 = __expf(lrelu(g_es1[s0 * 4 + lane] + ed_l) - M);
            a1 = __expf(lrelu(g_es1[s1 * 4 + lane] + ed_l) - M);
        }
        float w0 = __shfl_sync(0xffffffffu, a0, myh);
        float w1 = __shfl_sync(0xffffffffu, a1, myh);
        ss += w0 + w1;
        const __half2* h0 = reinterpret_cast<const __half2*>(&raw0);
        const __half2* h1 = reinterpret_cast<const __half2*>(&raw1);
#pragma unroll
        for (int q = 0; q < 4; q++) {
            float2 f0 = __half22float2(h0[q]);
            float2 f1 = __half22float2(h1[q]);
            acc[2 * q]     = fmaf(w0, f0.x, fmaf(w1, f1.x, acc[2 * q]));
            acc[2 * q + 1] = fmaf(w0, f0.y, fmaf(w1, f1.y, acc[2 * q + 1]));
        }
    }
    if (j < end) {
        int s0 = g_csr_src[j];
        float4 raw0 = *reinterpret_cast<const float4*>(&g_h1h[(size_t)s0 * 256 + lane * 8]);
        float a0 = 0.f;
        if (lane < 4) a0 = __expf(lrelu(g_es1[s0 * 4 + lane] + ed_l) - M);
        float w0 = __shfl_sync(0xffffffffu, a0, myh);
        ss += w0;
        const __half2* h0 = reinterpret_cast<const __half2*>(&raw0);
#pragma unroll
        for (int q = 0; q < 4; q++) {
            float2 f0 = __half22float2(h0[q]);
            acc[2 * q]     = fmaf(w0, f0.x, acc[2 * q]);
            acc[2 * q + 1] = fmaf(w0, f0.y, acc[2 * q + 1]);
        }
    }
    float inv = 1.f / (ss + 1e-8f);
    union { uint4 u; __half2 h2[4]; } pk;
#pragma unroll
    for (int q = 0; q < 4; q++) {
        float ox = acc[2 * q] * inv, oy = acc[2 * q + 1] * inv;
        ox = (ox > 0.f) ? ox : expm1f(ox);
        oy = (oy > 0.f) ? oy : expm1f(oy);
        pk.h2[q] = __floats2half2_rn(ox, oy);
    }
    __stcs(reinterpret_cast<uint4*>(&g_out1eh[(size_t)d * 256 + lane * 8]), pk.u);
}

// ---------------- GEMM2 (4 rows/iter): h2 = out1e @ W2, es2/ed2 + node maxes -----
__global__ void __launch_bounds__(256) k_gemm2(
    const float* __restrict__ W2, const float* __restrict__ a2) {
    __shared__ float xs[4][256];
    __shared__ float red[4][256];
    __shared__ float r2l[8], r2r[8];
    int t = threadIdx.x;
    int f = t & 63, ks = t >> 6;
    float Wreg[64];
#pragma unroll
    for (int kk = 0; kk < 64; kk++) Wreg[kk] = W2[(ks * 64 + kk) * 64 + f];
    float al = a2[f];
    float ar = a2[64 + f];
    int lane = t & 31, wid = t >> 5;
    float mx_es = -3.4e38f, mx_ed = -3.4e38f;
    for (int row0 = blockIdx.x * 4; row0 < NN; row0 += gridDim.x * 4) {
        __syncthreads();
#pragma unroll
        for (int rr = 0; rr < 4; rr++)
            xs[rr][t] = __half2float(__ldcs(&g_out1eh[(size_t)(row0 + rr) * 256 + t]));
        __syncthreads();
        float acc[4] = {0.f, 0.f, 0.f, 0.f};
#pragma unroll
        for (int kk = 0; kk < 64; kk++) {
            float w = Wreg[kk];
            int kidx = ks * 64 + kk;
            acc[0] = fmaf(xs[0][kidx], w, acc[0]);
            acc[1] = fmaf(xs[1][kidx], w, acc[1]);
            acc[2] = fmaf(xs[2][kidx], w, acc[2]);
            acc[3] = fmaf(xs[3][kidx], w, acc[3]);
        }
#pragma unroll
        for (int rr = 0; rr < 4; rr++) red[rr][t] = acc[rr];
        __syncthreads();
        // 256 threads: each produces one (row, feature) output
        {
            int rr = t >> 6, ff = t & 63;
            float val = red[rr][ff] + red[rr][64 + ff] + red[rr][128 + ff] + red[rr][192 + ff];
            g_h2h[(size_t)(row0 + rr) * 64 + ff] = __float2half(val);
            float vl = val * a2[ff];
            float vr = val * a2[64 + ff];
#pragma unroll
            for (int o = 16; o > 0; o >>= 1) {
                vl += __shfl_down_sync(0xffffffffu, vl, o);
                vr += __shfl_down_sync(0xffffffffu, vr, o);
            }
            if (lane == 0) { r2l[wid] = vl; r2r[wid] = vr; }
        }
        __syncthreads();
        if (t < 4) {
            float es = r2l[2 * t] + r2l[2 * t + 1];
            float ed = r2r[2 * t] + r2r[2 * t + 1];
            g_es2[row0 + t] = es;
            g_ed2[row0 + t] = ed;
            mx_es = fmaxf(mx_es, es);
            mx_ed = fmaxf(mx_ed, ed);
        }
    }
    if (t < 4) {
        atomicMax(&g_maxes2_u, enc_f(mx_es));
        atomicMax(&g_maxed2_u, enc_f(mx_ed));
    }
}

// ---------------- layer-2 aggregation: warp/dst, unroll-2, residual --------------
__global__ void __launch_bounds__(256) k_agg2(
    const float* __restrict__ user, const float* __restrict__ item) {
    int gw = (blockIdx.x * 256 + threadIdx.x) >> 5;
    int lane = threadIdx.x & 31;
    if (gw >= NN) return;
    int d = gw;
    int n0 = g_off[d];
    int cnt = g_cnt[d];
    float M = lrelu(dec_f(g_maxes2_u) + dec_f(g_maxed2_u));
    float2 acc = make_float2(0.f, 0.f);
    float ss = 0.f;
    float ed_d = g_ed2[d];
    int j = n0, end = n0 + cnt;
    for (; j + 1 < end; j += 2) {
        int s0 = g_csr_src[j];
        int s1 = g_csr_src[j + 1];
        __half2 hr0 = *reinterpret_cast<const __half2*>(&g_h2h[(size_t)s0 * 64 + lane * 2]);
        __half2 hr1 = *reinterpret_cast<const __half2*>(&g_h2h[(size_t)s1 * 64 + lane * 2]);
        float a = 0.f;
        if (lane < 2) {
            int sl = (lane == 0) ? s0 : s1;
            a = __expf(lrelu(g_es2[sl] + ed_d) - M);
        }
        float w0 = __shfl_sync(0xffffffffu, a, 0);
        float w1 = __shfl_sync(0xffffffffu, a, 1);
        ss += w0 + w1;
        float2 f0 = __half22float2(hr0);
        float2 f1 = __half22float2(hr1);
        acc.x = fmaf(w0, f0.x, fmaf(w1, f1.x, acc.x));
        acc.y = fmaf(w0, f0.y, fmaf(w1, f1.y, acc.y));
    }
    if (j < end) {
        int s0 = g_csr_src[j];
        __half2 hr0 = *reinterpret_cast<const __half2*>(&g_h2h[(size_t)s0 * 64 + lane * 2]);
        float a = 0.f;
        if (lane == 0) a = __expf(lrelu(g_es2[s0] + ed_d) - M);
        float w0 = __shfl_sync(0xffffffffu, a, 0);
        ss += w0;
        float2 f0 = __half22float2(hr0);
        acc.x = fmaf(w0, f0.x, acc.x);
        acc.y = fmaf(w0, f0.y, acc.y);
    }
    float inv = 1.f / (ss + 1e-8f);
    float2 emb = (d < NUSERS)
        ? *reinterpret_cast<const float2*>(&user[(size_t)d * 64 + lane * 2])
        : *reinterpret_cast<const float2*>(&item[(size_t)(d - NUSERS) * 64 + lane * 2]);
    float2 out = make_float2(acc.x * inv + emb.x, acc.y * inv + emb.y);
    *reinterpret_cast<float2*>(&g_out2[(size_t)d * 64 + lane * 2]) = out;
}

// ---------------- final scoring -----------------------------------------------------
__global__ void k_final(const int* __restrict__ uid, const int* __restrict__ iid,
                        float* __restrict__ out) {
    int gw = (blockIdx.x * blockDim.x + threadIdx.x) >> 5;
    int lane = threadIdx.x & 31;
    if (gw >= NB) return;
    int u = uid[gw];
    int it = NUSERS + iid[gw];
    float p = 0.f;
#pragma unroll
    for (int i = 0; i < 2; i++) {
        int f = i * 32 + lane;
        p += g_out2[(size_t)u * 64 + f] * g_out2[(size_t)it * 64 + f];
    }
#pragma unroll
    for (int o = 16; o > 0; o >>= 1) p += __shfl_down_sync(0xffffffffu, p, o);
    if (lane == 0) out[gw] = p;
}

// ---------------- launch --------------------------------------------------------------
extern "C" void kernel_launch(void* const* d_in, const int* in_sizes, int n_in,
                              void* d_out, int out_size) {
    const float* user = (const float*)d_in[0];
    const float* item = (const float*)d_in[1];
    const float* W1 = (const float*)d_in[2];
    const float* a1 = (const float*)d_in[3];
    const float* W2 = (const float*)d_in[4];
    const float* a2 = (const float*)d_in[5];
    const int* ei = (const int*)d_in[6];
    const int* uid = (const int*)d_in[7];
    const int* iid = (const int*)d_in[8];
    float* out = (float*)d_out;

    k_init<<<(NN + 255) / 256, 256>>>();
    k_hist<<<2048, 256>>>(ei);
    k_scan_block<<<NBLK_SCAN, 1024>>>();
    k_scan_top<<<1, 256>>>();
    k_scan_add<<<(NN + 255) / 256, 256>>>();
    k_scatter<<<(NE + 255) / 256, 256>>>(ei);
    k_gemm1<<<1184, 256>>>(user, item, W1, a1);
    k_agg1<<<(NN * 32 + 255) / 256, 256>>>();
    k_gemm2<<<1184, 256>>>(W2, a2);
    k_agg2<<<(NN * 32 + 255) / 256, 256>>>(user, item);
    k_final<<<NB * 32 / 256, 256>>>(uid, iid, out);
}

// round 5
// speedup vs baseline: 5.8153x; 1.7738x over previous
#include <cuda_runtime.h>
#include <cuda_fp16.h>

#define NUSERS 100000
#define NITEMS 50000
#define NN     150000
#define NN_PAD 150016   // multiple of 128
#define EMB    64
#define NE     2000000
#define NB     16384
#define NBLK_SCAN 147   // ceil(NN/1024)

// ---------------- scratch (device globals) ----------------------------------
__device__ __half g_xh[(size_t)NN_PAD * 64];    // input embeddings fp16 (pad rows zero)
__device__ __half g_w1t[256 * 64];              // W1^T: [n=256][k=64] fp16
__device__ __half g_w2t[64 * 256];              // W2^T: [n=64][k=256] fp16
__device__ __half g_h1h[(size_t)NN_PAD * 256];  // layer-1 features fp16
__device__ __half g_out1eh[(size_t)NN_PAD * 256]; // elu(agg1), fp16 (pad rows zero)
__device__ float  g_es1[NN * 4];
__device__ float  g_ed1[NN * 4];
__device__ __half g_h2h[(size_t)NN_PAD * 64];   // layer-2 features fp16
__device__ float  g_out2[(size_t)NN * 64];
__device__ float  g_es2[NN];
__device__ float  g_ed2[NN];
__device__ unsigned g_maxes1_u, g_maxed1_u;
__device__ unsigned g_maxes2_u, g_maxed2_u;

// CSR by dst
__device__ int g_cnt[NN];
__device__ int g_off[NN];
__device__ int g_cur[NN];
__device__ int g_csr_src[NE];
__device__ int g_bsum[NBLK_SCAN];
__device__ int g_btop[NBLK_SCAN];

__device__ __forceinline__ unsigned enc_f(float f) {
    unsigned u = __float_as_uint(f);
    return (u & 0x80000000u) ? ~u : (u | 0x80000000u);
}
__device__ __forceinline__ float dec_f(unsigned u) {
    return (u & 0x80000000u) ? __uint_as_float(u ^ 0x80000000u) : __uint_as_float(~u);
}
__device__ __forceinline__ float lrelu(float v) { return (v > 0.f) ? v : 0.2f * v; }

__device__ __forceinline__ void mma16816(float& d0, float& d1, float& d2, float& d3,
                                         unsigned a0, unsigned a1, unsigned a2, unsigned a3,
                                         unsigned b0, unsigned b1) {
    asm volatile(
        "mma.sync.aligned.m16n8k16.row.col.f32.f16.f16.f32 "
        "{%0,%1,%2,%3},{%4,%5,%6,%7},{%8,%9},{%0,%1,%2,%3};"
        : "+f"(d0), "+f"(d1), "+f"(d2), "+f"(d3)
        : "r"(a0), "r"(a1), "r"(a2), "r"(a3), "r"(b0), "r"(b1));
}
__device__ __forceinline__ unsigned lds_u32(const __half* p) {
    return *reinterpret_cast<const unsigned*>(p);
}

// ---------------- init ---------------------------------------------------------
__global__ void k_init() {
    int i = blockIdx.x * blockDim.x + threadIdx.x;
    if (i < NN) g_cnt[i] = 0;
    // zero pad rows of out1eh (GEMM2 reads them)
    if (i < (NN_PAD - NN) * 256 / 2)
        reinterpret_cast<unsigned*>(&g_out1eh[(size_t)NN * 256])[i] = 0;
    if (i == 0) {
        g_maxes1_u = 0x007FFFFFu; g_maxed1_u = 0x007FFFFFu;
        g_maxes2_u = 0x007FFFFFu; g_maxed2_u = 0x007FFFFFu;
    }
}

// ---------------- convert x to fp16 (padded) ------------------------------------
__global__ void k_cvt_x(const float* __restrict__ user, const float* __restrict__ item) {
    for (size_t i = (size_t)blockIdx.x * blockDim.x + threadIdx.x;
         i < (size_t)NN_PAD * 64; i += (size_t)gridDim.x * blockDim.x) {
        int row = (int)(i >> 6);
        float v = 0.f;
        if (row < NUSERS) v = user[i];
        else if (row < NN) v = item[i - (size_t)NUSERS * 64];
        g_xh[i] = __float2half(v);
    }
}

// ---------------- convert weights (transposed, fp16) -----------------------------
__global__ void k_cvt_w(const float* __restrict__ W1, const float* __restrict__ W2) {
    int i = blockIdx.x * blockDim.x + threadIdx.x;
    if (i < 256 * 64) {                 // w1t[n][k] = W1[k][n], n<256, k<64
        int n = i >> 6, k = i & 63;
        g_w1t[i] = __float2half(W1[k * 256 + n]);
    }
    if (i < 64 * 256) {                 // w2t[n][k] = W2[k][n], n<64, k<256
        int n = i >> 8, k = i & 255;
        g_w2t[i] = __float2half(W2[k * 64 + n]);
    }
}

// ---------------- histogram / scan / scatter (CSR build) -------------------------
__global__ void k_hist(const int* __restrict__ ei) {
    for (int e = blockIdx.x * 256 + threadIdx.x; e < NE; e += gridDim.x * 256)
        atomicAdd(&g_cnt[ei[NE + e]], 1);
}

__global__ void __launch_bounds__(1024) k_scan_block() {
    __shared__ int sh[1024];
    int t = threadIdx.x;
    int i = blockIdx.x * 1024 + t;
    int v = (i < NN) ? g_cnt[i] : 0;
    sh[t] = v;
    __syncthreads();
#pragma unroll
    for (int o = 1; o < 1024; o <<= 1) {
        int x = (t >= o) ? sh[t - o] : 0;
        __syncthreads();
        sh[t] += x;
        __syncthreads();
    }
    if (i < NN) g_off[i] = sh[t] - v;
    if (t == 1023) g_bsum[blockIdx.x] = sh[1023];
}

__global__ void __launch_bounds__(256) k_scan_top() {
    __shared__ int sh[256];
    int t = threadIdx.x;
    int v = (t < NBLK_SCAN) ? g_bsum[t] : 0;
    sh[t] = v;
    __syncthreads();
#pragma unroll
    for (int o = 1; o < 256; o <<= 1) {
        int x = (t >= o) ? sh[t - o] : 0;
        __syncthreads();
        sh[t] += x;
        __syncthreads();
    }
    if (t < NBLK_SCAN) g_btop[t] = sh[t] - v;
}

__global__ void k_scan_add() {
    int i = blockIdx.x * blockDim.x + threadIdx.x;
    if (i < NN) {
        int o = g_off[i] + g_btop[i >> 10];
        g_off[i] = o;
        g_cur[i] = o;
    }
}

__global__ void k_scatter(const int* __restrict__ ei) {
    int e = blockIdx.x * 256 + threadIdx.x;
    if (e >= NE) return;
    int d = ei[NE + e];
    int pos = atomicAdd(&g_cur[d], 1);
    g_csr_src[pos] = ei[e];
}

// ---------------- GEMM1 (tensor cores): h1 = x @ W1 ------------------------------
// block: 8 warps = 2 m-subtiles(16) x 4 n-subtiles(64); tile = m32 x n256, K=64.
__global__ void __launch_bounds__(256) k_gemm1_mma() {
    __shared__ __half As[32][72];
    __shared__ __half Bt[256][72];
    int t = threadIdx.x;
    int lane = t & 31, wid = t >> 5;
    int g = lane >> 2, tg = lane & 3;
    // load B once (W1^T [256][64])
#pragma unroll
    for (int i = 0; i < 8; i++) {
        int u = t + i * 256;
        int r = u >> 3, c = (u & 7) * 8;
        *reinterpret_cast<uint4*>(&Bt[r][c]) =
            *reinterpret_cast<const uint4*>(&g_w1t[r * 64 + c]);
    }
    int wm = (wid & 1) * 16;
    int wn = (wid >> 1) * 64;
    const int NT = NN_PAD / 32;
    for (int tile = blockIdx.x; tile < NT; tile += gridDim.x) {
        __syncthreads();
        {
            int r = t >> 3, c = (t & 7) * 8;
            *reinterpret_cast<uint4*>(&As[r][c]) =
                *reinterpret_cast<const uint4*>(&g_xh[(size_t)(tile * 32 + r) * 64 + c]);
        }
        __syncthreads();
        float acc[8][4];
#pragma unroll
        for (int ns = 0; ns < 8; ns++)
#pragma unroll
            for (int q = 0; q < 4; q++) acc[ns][q] = 0.f;
#pragma unroll
        for (int kt = 0; kt < 4; kt++) {
            int kb = kt * 16 + 2 * tg;
            unsigned a0 = lds_u32(&As[wm + g][kb]);
            unsigned a1 = lds_u32(&As[wm + g + 8][kb]);
            unsigned a2 = lds_u32(&As[wm + g][kb + 8]);
            unsigned a3 = lds_u32(&As[wm + g + 8][kb + 8]);
#pragma unroll
            for (int ns = 0; ns < 8; ns++) {
                unsigned b0 = lds_u32(&Bt[wn + ns * 8 + g][kb]);
                unsigned b1 = lds_u32(&Bt[wn + ns * 8 + g][kb + 8]);
                mma16816(acc[ns][0], acc[ns][1], acc[ns][2], acc[ns][3],
                         a0, a1, a2, a3, b0, b1);
            }
        }
        int row0 = tile * 32 + wm + g;
#pragma unroll
        for (int ns = 0; ns < 8; ns++) {
            int col = wn + ns * 8 + 2 * tg;
            if (row0 < NN)
                *reinterpret_cast<__half2*>(&g_h1h[(size_t)row0 * 256 + col]) =
                    __floats2half2_rn(acc[ns][0], acc[ns][1]);
            if (row0 + 8 < NN)
                *reinterpret_cast<__half2*>(&g_h1h[(size_t)(row0 + 8) * 256 + col]) =
                    __floats2half2_rn(acc[ns][2], acc[ns][3]);
        }
    }
}

// ---------------- es1/ed1 = h1 . a_l/a_r per head, + node maxes ------------------
__global__ void __launch_bounds__(256) k_edot1(const float* __restrict__ a1) {
    int gwarp = (blockIdx.x * 256 + threadIdx.x) >> 5;
    int nwarps = (gridDim.x * 256) >> 5;
    int lane = threadIdx.x & 31;
    int head = lane >> 3;
    int fo = (lane & 7) * 8;
    float al[8], ar[8];
#pragma unroll
    for (int i = 0; i < 8; i++) {
        al[i] = a1[head * 128 + fo + i];
        ar[i] = a1[head * 128 + 64 + fo + i];
    }
    float mx_es = -3.4e38f, mx_ed = -3.4e38f;
    for (int node = gwarp; node < NN; node += nwarps) {
        uint4 raw = *reinterpret_cast<const uint4*>(&g_h1h[(size_t)node * 256 + lane * 8]);
        const __half2* hp = reinterpret_cast<const __half2*>(&raw);
        float es = 0.f, ed = 0.f;
#pragma unroll
        for (int q = 0; q < 4; q++) {
            float2 hf = __half22float2(hp[q]);
            es = fmaf(hf.x, al[2 * q], fmaf(hf.y, al[2 * q + 1], es));
            ed = fmaf(hf.x, ar[2 * q], fmaf(hf.y, ar[2 * q + 1], ed));
        }
#pragma unroll
        for (int o = 1; o < 8; o <<= 1) {
            es += __shfl_xor_sync(0xffffffffu, es, o);
            ed += __shfl_xor_sync(0xffffffffu, ed, o);
        }
        if ((lane & 7) == 0) {
            g_es1[node * 4 + head] = es;
            g_ed1[node * 4 + head] = ed;
        }
        mx_es = fmaxf(mx_es, es);
        mx_ed = fmaxf(mx_ed, ed);
    }
#pragma unroll
    for (int o = 16; o > 0; o >>= 1) {
        mx_es = fmaxf(mx_es, __shfl_xor_sync(0xffffffffu, mx_es, o));
        mx_ed = fmaxf(mx_ed, __shfl_xor_sync(0xffffffffu, mx_ed, o));
    }
    if (lane == 0) {
        atomicMax(&g_maxes1_u, enc_f(mx_es));
        atomicMax(&g_maxed1_u, enc_f(mx_ed));
    }
}

// ---------------- layer-1 aggregation: warp/dst, unroll-4, fused elu -------------
__global__ void __launch_bounds__(256) k_agg1() {
    int gw = (blockIdx.x * 256 + threadIdx.x) >> 5;
    int lane = threadIdx.x & 31;
    if (gw >= NN) return;
    int d = gw;
    int n0 = g_off[d];
    int cnt = g_cnt[d];
    float M = lrelu(dec_f(g_maxes1_u) + dec_f(g_maxed1_u));
    float acc[8] = {0.f, 0.f, 0.f, 0.f, 0.f, 0.f, 0.f, 0.f};
    float ss = 0.f;
    int myh = lane >> 3;
    float ed_l = (lane < 4) ? g_ed1[d * 4 + lane] : 0.f;
    int j = n0, end = n0 + cnt;
    for (; j + 3 < end; j += 4) {
        int s0 = g_csr_src[j], s1 = g_csr_src[j + 1];
        int s2 = g_csr_src[j + 2], s3 = g_csr_src[j + 3];
        float4 r0 = *reinterpret_cast<const float4*>(&g_h1h[(size_t)s0 * 256 + lane * 8]);
        float4 r1 = *reinterpret_cast<const float4*>(&g_h1h[(size_t)s1 * 256 + lane * 8]);
        float4 r2 = *reinterpret_cast<const float4*>(&g_h1h[(size_t)s2 * 256 + lane * 8]);
        float4 r3 = *reinterpret_cast<const float4*>(&g_h1h[(size_t)s3 * 256 + lane * 8]);
        float a0 = 0.f, a1v = 0.f, a2v = 0.f, a3v = 0.f;
        if (lane < 4) {
            a0 = __expf(lrelu(g_es1[s0 * 4 + lane] + ed_l) - M);
            a1v = __expf(lrelu(g_es1[s1 * 4 + lane] + ed_l) - M);
            a2v = __expf(lrelu(g_es1[s2 * 4 + lane] + ed_l) - M);
            a3v = __expf(lrelu(g_es1[s3 * 4 + lane] + ed_l) - M);
        }
        float w0 = __shfl_sync(0xffffffffu, a0, myh);
        float w1 = __shfl_sync(0xffffffffu, a1v, myh);
        float w2 = __shfl_sync(0xffffffffu, a2v, myh);
        float w3 = __shfl_sync(0xffffffffu, a3v, myh);
        ss += (w0 + w1) + (w2 + w3);
        const __half2* h0 = reinterpret_cast<const __half2*>(&r0);
        const __half2* h1 = reinterpret_cast<const __half2*>(&r1);
        const __half2* h2 = reinterpret_cast<const __half2*>(&r2);
        const __half2* h3 = reinterpret_cast<const __half2*>(&r3);
#pragma unroll
        for (int q = 0; q < 4; q++) {
            float2 f0 = __half22float2(h0[q]);
            float2 f1 = __half22float2(h1[q]);
            float2 f2 = __half22float2(h2[q]);
            float2 f3 = __half22float2(h3[q]);
            acc[2 * q]     = fmaf(w0, f0.x, fmaf(w1, f1.x, fmaf(w2, f2.x, fmaf(w3, f3.x, acc[2 * q]))));
            acc[2 * q + 1] = fmaf(w0, f0.y, fmaf(w1, f1.y, fmaf(w2, f2.y, fmaf(w3, f3.y, acc[2 * q + 1]))));
        }
    }
    for (; j < end; j++) {
        int s0 = g_csr_src[j];
        float4 r0 = *reinterpret_cast<const float4*>(&g_h1h[(size_t)s0 * 256 + lane * 8]);
        float a0 = 0.f;
        if (lane < 4) a0 = __expf(lrelu(g_es1[s0 * 4 + lane] + ed_l) - M);
        float w0 = __shfl_sync(0xffffffffu, a0, myh);
        ss += w0;
        const __half2* h0 = reinterpret_cast<const __half2*>(&r0);
#pragma unroll
        for (int q = 0; q < 4; q++) {
            float2 f0 = __half22float2(h0[q]);
            acc[2 * q]     = fmaf(w0, f0.x, acc[2 * q]);
            acc[2 * q + 1] = fmaf(w0, f0.y, acc[2 * q + 1]);
        }
    }
    float inv = 1.f / (ss + 1e-8f);
    union { uint4 u; __half2 h2[4]; } pk;
#pragma unroll
    for (int q = 0; q < 4; q++) {
        float ox = acc[2 * q] * inv, oy = acc[2 * q + 1] * inv;
        ox = (ox > 0.f) ? ox : expm1f(ox);
        oy = (oy > 0.f) ? oy : expm1f(oy);
        pk.h2[q] = __floats2half2_rn(ox, oy);
    }
    __stcs(reinterpret_cast<uint4*>(&g_out1eh[(size_t)d * 256 + lane * 8]), pk.u);
}

// ---------------- GEMM2 (tensor cores): h2 = out1e @ W2 --------------------------
// block: 8 warps, each m16 x n64; tile = m128 x n64, K=256 in 4 chunks of 64.
__global__ void __launch_bounds__(256) k_gemm2_mma() {
    __shared__ __half As[128][72];
    __shared__ __half Bt[64][72];
    int t = threadIdx.x;
    int lane = t & 31, wid = t >> 5;
    int g = lane >> 2, tg = lane & 3;
    int wm = wid * 16;
    const int NT = NN_PAD / 128;
    for (int tile = blockIdx.x; tile < NT; tile += gridDim.x) {
        float acc[8][4];
#pragma unroll
        for (int ns = 0; ns < 8; ns++)
#pragma unroll
            for (int q = 0; q < 4; q++) acc[ns][q] = 0.f;
#pragma unroll
        for (int kc = 0; kc < 4; kc++) {
            __syncthreads();
#pragma unroll
            for (int i = 0; i < 4; i++) {           // A chunk: 128 x 64
                int u = t + i * 256;
                int r = u >> 3, c = (u & 7) * 8;
                *reinterpret_cast<uint4*>(&As[r][c]) =
                    *reinterpret_cast<const uint4*>(
                        &g_out1eh[(size_t)(tile * 128 + r) * 256 + kc * 64 + c]);
            }
#pragma unroll
            for (int i = 0; i < 2; i++) {           // B chunk: [64 n][64 k]
                int u = t + i * 256;
                int r = u >> 3, c = (u & 7) * 8;
                *reinterpret_cast<uint4*>(&Bt[r][c]) =
                    *reinterpret_cast<const uint4*>(&g_w2t[r * 256 + kc * 64 + c]);
            }
            __syncthreads();
#pragma unroll
            for (int kt = 0; kt < 4; kt++) {
                int kb = kt * 16 + 2 * tg;
                unsigned a0 = lds_u32(&As[wm + g][kb]);
                unsigned a1 = lds_u32(&As[wm + g + 8][kb]);
                unsigned a2 = lds_u32(&As[wm + g][kb + 8]);
                unsigned a3 = lds_u32(&As[wm + g + 8][kb + 8]);
#pragma unroll
                for (int ns = 0; ns < 8; ns++) {
                    unsigned b0 = lds_u32(&Bt[ns * 8 + g][kb]);
                    unsigned b1 = lds_u32(&Bt[ns * 8 + g][kb + 8]);
                    mma16816(acc[ns][0], acc[ns][1], acc[ns][2], acc[ns][3],
                             a0, a1, a2, a3, b0, b1);
                }
            }
        }
        int row0 = tile * 128 + wm + g;
#pragma unroll
        for (int ns = 0; ns < 8; ns++) {
            int col = ns * 8 + 2 * tg;
            if (row0 < NN)
                *reinterpret_cast<__half2*>(&g_h2h[(size_t)row0 * 64 + col]) =
                    __floats2half2_rn(acc[ns][0], acc[ns][1]);
            if (row0 + 8 < NN)
                *reinterpret_cast<__half2*>(&g_h2h[(size_t)(row0 + 8) * 64 + col]) =
                    __floats2half2_rn(acc[ns][2], acc[ns][3]);
        }
    }
}

// ---------------- es2/ed2 = h2 . a2_l/a2_r, + node maxes -------------------------
__global__ void __launch_bounds__(256) k_edot2(const float* __restrict__ a2) {
    int gwarp = (blockIdx.x * 256 + threadIdx.x) >> 5;
    int nwarps = (gridDim.x * 256) >> 5;
    int lane = threadIdx.x & 31;
    float2 al = *reinterpret_cast<const float2*>(&a2[lane * 2]);
    float2 ar = *reinterpret_cast<const float2*>(&a2[64 + lane * 2]);
    float mx_es = -3.4e38f, mx_ed = -3.4e38f;
    for (int node = gwarp; node < NN; node += nwarps) {
        float2 hf = __half22float2(
            *reinterpret_cast<const __half2*>(&g_h2h[(size_t)node * 64 + lane * 2]));
        float es = fmaf(hf.x, al.x, hf.y * al.y);
        float ed = fmaf(hf.x, ar.x, hf.y * ar.y);
#pragma unroll
        for (int o = 1; o < 32; o <<= 1) {
            es += __shfl_xor_sync(0xffffffffu, es, o);
            ed += __shfl_xor_sync(0xffffffffu, ed, o);
        }
        if (lane == 0) { g_es2[node] = es; g_ed2[node] = ed; }
        mx_es = fmaxf(mx_es, es);
        mx_ed = fmaxf(mx_ed, ed);
    }
    if (lane == 0) {
        atomicMax(&g_maxes2_u, enc_f(mx_es));
        atomicMax(&g_maxed2_u, enc_f(mx_ed));
    }
}

// ---------------- layer-2 aggregation: warp/dst, unroll-2, residual --------------
__global__ void __launch_bounds__(256) k_agg2(
    const float* __restrict__ user, const float* __restrict__ item) {
    int gw = (blockIdx.x * 256 + threadIdx.x) >> 5;
    int lane = threadIdx.x & 31;
    if (gw >= NN) return;
    int d = gw;
    int n0 = g_off[d];
    int cnt = g_cnt[d];
    float M = lrelu(dec_f(g_maxes2_u) + dec_f(g_maxed2_u));
    float2 acc = make_float2(0.f, 0.f);
    float ss = 0.f;
    float ed_d = g_ed2[d];
    int j = n0, end = n0 + cnt;
    for (; j + 1 < end; j += 2) {
        int s0 = g_csr_src[j];
        int s1 = g_csr_src[j + 1];
        __half2 hr0 = *reinterpret_cast<const __half2*>(&g_h2h[(size_t)s0 * 64 + lane * 2]);
        __half2 hr1 = *reinterpret_cast<const __half2*>(&g_h2h[(size_t)s1 * 64 + lane * 2]);
        float a = 0.f;
        if (lane < 2) {
            int sl = (lane == 0) ? s0 : s1;
            a = __expf(lrelu(g_es2[sl] + ed_d) - M);
        }
        float w0 = __shfl_sync(0xffffffffu, a, 0);
        float w1 = __shfl_sync(0xffffffffu, a, 1);
        ss += w0 + w1;
        float2 f0 = __half22float2(hr0);
        float2 f1 = __half22float2(hr1);
        acc.x = fmaf(w0, f0.x, fmaf(w1, f1.x, acc.x));
        acc.y = fmaf(w0, f0.y, fmaf(w1, f1.y, acc.y));
    }
    if (j < end) {
        int s0 = g_csr_src[j];
        __half2 hr0 = *reinterpret_cast<const __half2*>(&g_h2h[(size_t)s0 * 64 + lane * 2]);
        float a = 0.f;
        if (lane == 0) a = __expf(lrelu(g_es2[s0] + ed_d) - M);
        float w0 = __shfl_sync(0xffffffffu, a, 0);
        ss += w0;
        float2 f0 = __half22float2(hr0);
        acc.x = fmaf(w0, f0.x, acc.x);
        acc.y = fmaf(w0, f0.y, acc.y);
    }
    float inv = 1.f / (ss + 1e-8f);
    float2 emb = (d < NUSERS)
        ? *reinterpret_cast<const float2*>(&user[(size_t)d * 64 + lane * 2])
        : *reinterpret_cast<const float2*>(&item[(size_t)(d - NUSERS) * 64 + lane * 2]);
    float2 out = make_float2(acc.x * inv + emb.x, acc.y * inv + emb.y);
    *reinterpret_cast<float2*>(&g_out2[(size_t)d * 64 + lane * 2]) = out;
}

// ---------------- final scoring -----------------------------------------------------
__global__ void k_final(const int* __restrict__ uid, const int* __restrict__ iid,
                        float* __restrict__ out) {
    int gw = (blockIdx.x * blockDim.x + threadIdx.x) >> 5;
    int lane = threadIdx.x & 31;
    if (gw >= NB) return;
    int u = uid[gw];
    int it = NUSERS + iid[gw];
    float p = 0.f;
#pragma unroll
    for (int i = 0; i < 2; i++) {
        int f = i * 32 + lane;
        p += g_out2[(size_t)u * 64 + f] * g_out2[(size_t)it * 64 + f];
    }
#pragma unroll
    for (int o = 16; o > 0; o >>= 1) p += __shfl_down_sync(0xffffffffu, p, o);
    if (lane == 0) out[gw] = p;
}

// ---------------- launch --------------------------------------------------------------
extern "C" void kernel_launch(void* const* d_in, const int* in_sizes, int n_in,
                              void* d_out, int out_size) {
    const float* user = (const float*)d_in[0];
    const float* item = (const float*)d_in[1];
    const float* W1 = (const float*)d_in[2];
    const float* a1 = (const float*)d_in[3];
    const float* W2 = (const float*)d_in[4];
    const float* a2 = (const float*)d_in[5];
    const int* ei = (const int*)d_in[6];
    const int* uid = (const int*)d_in[7];
    const int* iid = (const int*)d_in[8];
    float* out = (float*)d_out;

    k_init<<<(NN + 255) / 256, 256>>>();
    k_cvt_x<<<2048, 256>>>(user, item);
    k_cvt_w<<<64, 256>>>(W1, W2);
    k_hist<<<2048, 256>>>(ei);
    k_scan_block<<<NBLK_SCAN, 1024>>>();
    k_scan_top<<<1, 256>>>();
    k_scan_add<<<(NN + 255) / 256, 256>>>();
    k_scatter<<<(NE + 255) / 256, 256>>>(ei);
    k_gemm1_mma<<<296, 256>>>();
    k_edot1<<<512, 256>>>(a1);
    k_agg1<<<(NN * 32 + 255) / 256, 256>>>();
    k_gemm2_mma<<<296, 256>>>();
    k_edot2<<<512, 256>>>(a2);
    k_agg2<<<(NN * 32 + 255) / 256, 256>>>(user, item);
    k_final<<<NB * 32 / 256, 256>>>(uid, iid, out);
}

// round 6
// speedup vs baseline: 6.8380x; 1.1759x over previous
#include <cuda_runtime.h>
#include <cuda_fp16.h>

#define NUSERS 100000
#define NITEMS 50000
#define NN     150000
#define NN_PAD 150016   // multiple of 128
#define EMB    64
#define NE     2000000
#define NB     16384
#define NBLK_SCAN 147   // ceil(NN/1024)

// ---------------- scratch (device globals) ----------------------------------
__device__ __half g_xh[(size_t)NN_PAD * 64];      // input embeddings fp16 (pad rows zero)
__device__ __half g_w1t[256 * 64];                // W1^T: [n=256][k=64] fp16
__device__ __half g_w2t[64 * 256];                // W2^T: [n=64][k=256] fp16
__device__ __half g_h1h[(size_t)NN_PAD * 256];    // layer-1 features fp16
__device__ __half g_out1eh[(size_t)NN_PAD * 256]; // elu(agg1), fp16 (pad rows zero)
__device__ float  g_es1[NN * 4];
__device__ float  g_ed1[NN * 4];
__device__ __half g_h2h[(size_t)NN_PAD * 64];     // layer-2 features fp16
__device__ float  g_out2[(size_t)NN * 64];
__device__ float  g_es2[NN];
__device__ float  g_ed2[NN];
__device__ unsigned g_maxes1_u, g_maxed1_u;
__device__ unsigned g_maxes2_u, g_maxed2_u;

// CSR by dst
__device__ int g_cnt[NN];
__device__ int g_off[NN];
__device__ int g_cur[NN];
__device__ int g_csr_src[NE];
__device__ int g_bsum[NBLK_SCAN];
__device__ int g_btop[NBLK_SCAN];

__device__ __forceinline__ unsigned enc_f(float f) {
    unsigned u = __float_as_uint(f);
    return (u & 0x80000000u) ? ~u : (u | 0x80000000u);
}
__device__ __forceinline__ float dec_f(unsigned u) {
    return (u & 0x80000000u) ? __uint_as_float(u ^ 0x80000000u) : __uint_as_float(~u);
}
__device__ __forceinline__ float lrelu(float v) { return (v > 0.f) ? v : 0.2f * v; }

__device__ __forceinline__ void mma16816(float& d0, float& d1, float& d2, float& d3,
                                         unsigned a0, unsigned a1, unsigned a2, unsigned a3,
                                         unsigned b0, unsigned b1) {
    asm volatile(
        "mma.sync.aligned.m16n8k16.row.col.f32.f16.f16.f32 "
        "{%0,%1,%2,%3},{%4,%5,%6,%7},{%8,%9},{%0,%1,%2,%3};"
        : "+f"(d0), "+f"(d1), "+f"(d2), "+f"(d3)
        : "r"(a0), "r"(a1), "r"(a2), "r"(a3), "r"(b0), "r"(b1));
}
__device__ __forceinline__ unsigned lds_u32(const __half* p) {
    return *reinterpret_cast<const unsigned*>(p);
}

// ---------------- init ---------------------------------------------------------
__global__ void k_init() {
    int i = blockIdx.x * blockDim.x + threadIdx.x;
    if (i < NN) g_cnt[i] = 0;
    if (i < (NN_PAD - NN) * 256 / 2)
        reinterpret_cast<unsigned*>(&g_out1eh[(size_t)NN * 256])[i] = 0;
    if (i == 0) {
        g_maxes1_u = 0x007FFFFFu; g_maxed1_u = 0x007FFFFFu;
        g_maxes2_u = 0x007FFFFFu; g_maxed2_u = 0x007FFFFFu;
    }
}

// ---------------- convert x to fp16 (padded) ------------------------------------
__global__ void k_cvt_x(const float* __restrict__ user, const float* __restrict__ item) {
    for (size_t i = (size_t)blockIdx.x * blockDim.x + threadIdx.x;
         i < (size_t)NN_PAD * 64; i += (size_t)gridDim.x * blockDim.x) {
        int row = (int)(i >> 6);
        float v = 0.f;
        if (row < NUSERS) v = user[i];
        else if (row < NN) v = item[i - (size_t)NUSERS * 64];
        g_xh[i] = __float2half(v);
    }
}

// ---------------- convert weights (transposed, fp16) -----------------------------
__global__ void k_cvt_w(const float* __restrict__ W1, const float* __restrict__ W2) {
    int i = blockIdx.x * blockDim.x + threadIdx.x;
    if (i < 256 * 64) {
        int n = i >> 6, k = i & 63;
        g_w1t[i] = __float2half(W1[k * 256 + n]);
    }
    if (i < 64 * 256) {
        int n = i >> 8, k = i & 255;
        g_w2t[i] = __float2half(W2[k * 64 + n]);
    }
}

// ---------------- CSR build -------------------------------------------------------
__global__ void k_hist(const int* __restrict__ ei) {
    for (int e = blockIdx.x * 256 + threadIdx.x; e < NE; e += gridDim.x * 256)
        atomicAdd(&g_cnt[ei[NE + e]], 1);
}

__global__ void __launch_bounds__(1024) k_scan_block() {
    __shared__ int sh[1024];
    int t = threadIdx.x;
    int i = blockIdx.x * 1024 + t;
    int v = (i < NN) ? g_cnt[i] : 0;
    sh[t] = v;
    __syncthreads();
#pragma unroll
    for (int o = 1; o < 1024; o <<= 1) {
        int x = (t >= o) ? sh[t - o] : 0;
        __syncthreads();
        sh[t] += x;
        __syncthreads();
    }
    if (i < NN) g_off[i] = sh[t] - v;
    if (t == 1023) g_bsum[blockIdx.x] = sh[1023];
}

__global__ void __launch_bounds__(256) k_scan_top() {
    __shared__ int sh[256];
    int t = threadIdx.x;
    int v = (t < NBLK_SCAN) ? g_bsum[t] : 0;
    sh[t] = v;
    __syncthreads();
#pragma unroll
    for (int o = 1; o < 256; o <<= 1) {
        int x = (t >= o) ? sh[t - o] : 0;
        __syncthreads();
        sh[t] += x;
        __syncthreads();
    }
    if (t < NBLK_SCAN) g_btop[t] = sh[t] - v;
}

__global__ void k_scan_add() {
    int i = blockIdx.x * blockDim.x + threadIdx.x;
    if (i < NN) {
        int o = g_off[i] + g_btop[i >> 10];
        g_off[i] = o;
        g_cur[i] = o;
    }
}

__global__ void k_scatter(const int* __restrict__ ei) {
    int e = blockIdx.x * 256 + threadIdx.x;
    if (e >= NE) return;
    int d = ei[NE + e];
    int pos = atomicAdd(&g_cur[d], 1);
    g_csr_src[pos] = ei[e];
}

// ---------------- GEMM1 (tensor cores) + fused es1/ed1 epilogue ------------------
// block: 8 warps = 2 m-subtiles(16) x 4 n-subtiles(64); each warp's 64 cols = 1 head.
__global__ void __launch_bounds__(256) k_gemm1_mma(const float* __restrict__ a1) {
    __shared__ __half As[32][72];
    __shared__ __half Bt[256][72];
    int t = threadIdx.x;
    int lane = t & 31, wid = t >> 5;
    int g = lane >> 2, tg = lane & 3;
#pragma unroll
    for (int i = 0; i < 8; i++) {
        int u = t + i * 256;
        int r = u >> 3, c = (u & 7) * 8;
        *reinterpret_cast<uint4*>(&Bt[r][c]) =
            *reinterpret_cast<const uint4*>(&g_w1t[r * 64 + c]);
    }
    int wm = (wid & 1) * 16;
    int wn = (wid >> 1) * 64;
    int head = wid >> 1;
    // preload attention coefficients for this thread's columns
    float alc[8][2], arc[8][2];
#pragma unroll
    for (int ns = 0; ns < 8; ns++) {
#pragma unroll
        for (int c = 0; c < 2; c++) {
            int col = ns * 8 + 2 * tg + c;
            alc[ns][c] = a1[head * 128 + col];
            arc[ns][c] = a1[head * 128 + 64 + col];
        }
    }
    float mx_es = -3.4e38f, mx_ed = -3.4e38f;
    const int NT = NN_PAD / 32;
    for (int tile = blockIdx.x; tile < NT; tile += gridDim.x) {
        __syncthreads();
        {
            int r = t >> 3, c = (t & 7) * 8;
            *reinterpret_cast<uint4*>(&As[r][c]) =
                *reinterpret_cast<const uint4*>(&g_xh[(size_t)(tile * 32 + r) * 64 + c]);
        }
        __syncthreads();
        float acc[8][4];
#pragma unroll
        for (int ns = 0; ns < 8; ns++)
#pragma unroll
            for (int q = 0; q < 4; q++) acc[ns][q] = 0.f;
#pragma unroll
        for (int kt = 0; kt < 4; kt++) {
            int kb = kt * 16 + 2 * tg;
            unsigned a0 = lds_u32(&As[wm + g][kb]);
            unsigned a1f = lds_u32(&As[wm + g + 8][kb]);
            unsigned a2f = lds_u32(&As[wm + g][kb + 8]);
            unsigned a3f = lds_u32(&As[wm + g + 8][kb + 8]);
#pragma unroll
            for (int ns = 0; ns < 8; ns++) {
                unsigned b0 = lds_u32(&Bt[wn + ns * 8 + g][kb]);
                unsigned b1 = lds_u32(&Bt[wn + ns * 8 + g][kb + 8]);
                mma16816(acc[ns][0], acc[ns][1], acc[ns][2], acc[ns][3],
                         a0, a1f, a2f, a3f, b0, b1);
            }
        }
        int row0 = tile * 32 + wm + g;
        // store h1 (fp16)
#pragma unroll
        for (int ns = 0; ns < 8; ns++) {
            int col = wn + ns * 8 + 2 * tg;
            if (row0 < NN)
                *reinterpret_cast<__half2*>(&g_h1h[(size_t)row0 * 256 + col]) =
                    __floats2half2_rn(acc[ns][0], acc[ns][1]);
            if (row0 + 8 < NN)
                *reinterpret_cast<__half2*>(&g_h1h[(size_t)(row0 + 8) * 256 + col]) =
                    __floats2half2_rn(acc[ns][2], acc[ns][3]);
        }
        // fused es/ed epilogue: dot over this warp's 64 cols (one head)
        float es0 = 0.f, ed0 = 0.f, es8 = 0.f, ed8 = 0.f;
#pragma unroll
        for (int ns = 0; ns < 8; ns++) {
            es0 = fmaf(acc[ns][0], alc[ns][0], fmaf(acc[ns][1], alc[ns][1], es0));
            ed0 = fmaf(acc[ns][0], arc[ns][0], fmaf(acc[ns][1], arc[ns][1], ed0));
            es8 = fmaf(acc[ns][2], alc[ns][0], fmaf(acc[ns][3], alc[ns][1], es8));
            ed8 = fmaf(acc[ns][2], arc[ns][0], fmaf(acc[ns][3], arc[ns][1], ed8));
        }
#pragma unroll
        for (int o = 1; o < 4; o <<= 1) {
            es0 += __shfl_xor_sync(0xffffffffu, es0, o);
            ed0 += __shfl_xor_sync(0xffffffffu, ed0, o);
            es8 += __shfl_xor_sync(0xffffffffu, es8, o);
            ed8 += __shfl_xor_sync(0xffffffffu, ed8, o);
        }
        if (tg == 0) {
            if (row0 < NN) {
                g_es1[row0 * 4 + head] = es0;
                g_ed1[row0 * 4 + head] = ed0;
                mx_es = fmaxf(mx_es, es0);
                mx_ed = fmaxf(mx_ed, ed0);
            }
            if (row0 + 8 < NN) {
                g_es1[(row0 + 8) * 4 + head] = es8;
                g_ed1[(row0 + 8) * 4 + head] = ed8;
                mx_es = fmaxf(mx_es, es8);
                mx_ed = fmaxf(mx_ed, ed8);
            }
        }
    }
#pragma unroll
    for (int o = 16; o > 0; o >>= 1) {
        mx_es = fmaxf(mx_es, __shfl_xor_sync(0xffffffffu, mx_es, o));
        mx_ed = fmaxf(mx_ed, __shfl_xor_sync(0xffffffffu, mx_ed, o));
    }
    if (lane == 0) {
        atomicMax(&g_maxes1_u, enc_f(mx_es));
        atomicMax(&g_maxed1_u, enc_f(mx_ed));
    }
}

// ---------------- layer-1 aggregation: warp/dst, unroll-4, broadcast att ----------
__global__ void __launch_bounds__(256) k_agg1() {
    int gw = (blockIdx.x * 256 + threadIdx.x) >> 5;
    int lane = threadIdx.x & 31;
    if (gw >= NN) return;
    int d = gw;
    int n0 = g_off[d];
    int cnt = g_cnt[d];
    float M = lrelu(dec_f(g_maxes1_u) + dec_f(g_maxed1_u));
    float acc[8] = {0.f, 0.f, 0.f, 0.f, 0.f, 0.f, 0.f, 0.f};
    float ss = 0.f;
    int myh = lane >> 3;                // lane's head
    float ed_l = g_ed1[d * 4 + myh];    // broadcast within 8-lane group
    int j = n0, end = n0 + cnt;
    for (; j + 3 < end; j += 4) {
        int s0 = g_csr_src[j], s1 = g_csr_src[j + 1];
        int s2 = g_csr_src[j + 2], s3 = g_csr_src[j + 3];
        float4 r0 = *reinterpret_cast<const float4*>(&g_h1h[(size_t)s0 * 256 + lane * 8]);
        float4 r1 = *reinterpret_cast<const float4*>(&g_h1h[(size_t)s1 * 256 + lane * 8]);
        float4 r2 = *reinterpret_cast<const float4*>(&g_h1h[(size_t)s2 * 256 + lane * 8]);
        float4 r3 = *reinterpret_cast<const float4*>(&g_h1h[(size_t)s3 * 256 + lane * 8]);
        // every lane loads its head's logit directly (single-sector broadcast)
        float w0 = __expf(lrelu(g_es1[s0 * 4 + myh] + ed_l) - M);
        float w1 = __expf(lrelu(g_es1[s1 * 4 + myh] + ed_l) - M);
        float w2 = __expf(lrelu(g_es1[s2 * 4 + myh] + ed_l) - M);
        float w3 = __expf(lrelu(g_es1[s3 * 4 + myh] + ed_l) - M);
        ss += (w0 + w1) + (w2 + w3);
        const __half2* h0 = reinterpret_cast<const __half2*>(&r0);
        const __half2* h1 = reinterpret_cast<const __half2*>(&r1);
        const __half2* h2 = reinterpret_cast<const __half2*>(&r2);
        const __half2* h3 = reinterpret_cast<const __half2*>(&r3);
#pragma unroll
        for (int q = 0; q < 4; q++) {
            float2 f0 = __half22float2(h0[q]);
            float2 f1 = __half22float2(h1[q]);
            float2 f2 = __half22float2(h2[q]);
            float2 f3 = __half22float2(h3[q]);
            acc[2 * q]     = fmaf(w0, f0.x, fmaf(w1, f1.x, fmaf(w2, f2.x, fmaf(w3, f3.x, acc[2 * q]))));
            acc[2 * q + 1] = fmaf(w0, f0.y, fmaf(w1, f1.y, fmaf(w2, f2.y, fmaf(w3, f3.y, acc[2 * q + 1]))));
        }
    }
    for (; j < end; j++) {
        int s0 = g_csr_src[j];
        float4 r0 = *reinterpret_cast<const float4*>(&g_h1h[(size_t)s0 * 256 + lane * 8]);
        float w0 = __expf(lrelu(g_es1[s0 * 4 + myh] + ed_l) - M);
        ss += w0;
        const __half2* h0 = reinterpret_cast<const __half2*>(&r0);
#pragma unroll
        for (int q = 0; q < 4; q++) {
            float2 f0 = __half22float2(h0[q]);
            acc[2 * q]     = fmaf(w0, f0.x, acc[2 * q]);
            acc[2 * q + 1] = fmaf(w0, f0.y, acc[2 * q + 1]);
        }
    }
    float inv = 1.f / (ss + 1e-8f);
    union { uint4 u; __half2 h2[4]; } pk;
#pragma unroll
    for (int q = 0; q < 4; q++) {
        float ox = acc[2 * q] * inv, oy = acc[2 * q + 1] * inv;
        ox = (ox > 0.f) ? ox : expm1f(ox);
        oy = (oy > 0.f) ? oy : expm1f(oy);
        pk.h2[q] = __floats2half2_rn(ox, oy);
    }
    __stcs(reinterpret_cast<uint4*>(&g_out1eh[(size_t)d * 256 + lane * 8]), pk.u);
}

// ---------------- GEMM2 (tensor cores) + fused es2/ed2 epilogue -------------------
// block: 8 warps, each m16 x n64; tile = m128 x n64, K=256 in 4 chunks of 64.
__global__ void __launch_bounds__(256) k_gemm2_mma(const float* __restrict__ a2) {
    __shared__ __half As[128][72];
    __shared__ __half Bt[64][72];
    int t = threadIdx.x;
    int lane = t & 31, wid = t >> 5;
    int g = lane >> 2, tg = lane & 3;
    int wm = wid * 16;
    float alc[8][2], arc[8][2];
#pragma unroll
    for (int ns = 0; ns < 8; ns++) {
#pragma unroll
        for (int c = 0; c < 2; c++) {
            int col = ns * 8 + 2 * tg + c;
            alc[ns][c] = a2[col];
            arc[ns][c] = a2[64 + col];
        }
    }
    float mx_es = -3.4e38f, mx_ed = -3.4e38f;
    const int NT = NN_PAD / 128;
    for (int tile = blockIdx.x; tile < NT; tile += gridDim.x) {
        float acc[8][4];
#pragma unroll
        for (int ns = 0; ns < 8; ns++)
#pragma unroll
            for (int q = 0; q < 4; q++) acc[ns][q] = 0.f;
#pragma unroll
        for (int kc = 0; kc < 4; kc++) {
            __syncthreads();
#pragma unroll
            for (int i = 0; i < 4; i++) {
                int u = t + i * 256;
                int r = u >> 3, c = (u & 7) * 8;
                *reinterpret_cast<uint4*>(&As[r][c]) =
                    *reinterpret_cast<const uint4*>(
                        &g_out1eh[(size_t)(tile * 128 + r) * 256 + kc * 64 + c]);
            }
#pragma unroll
            for (int i = 0; i < 2; i++) {
                int u = t + i * 256;
                int r = u >> 3, c = (u & 7) * 8;
                *reinterpret_cast<uint4*>(&Bt[r][c]) =
                    *reinterpret_cast<const uint4*>(&g_w2t[r * 256 + kc * 64 + c]);
            }
            __syncthreads();
#pragma unroll
            for (int kt = 0; kt < 4; kt++) {
                int kb = kt * 16 + 2 * tg;
                unsigned a0 = lds_u32(&As[wm + g][kb]);
                unsigned a1f = lds_u32(&As[wm + g + 8][kb]);
                unsigned a2f = lds_u32(&As[wm + g][kb + 8]);
                unsigned a3f = lds_u32(&As[wm + g + 8][kb + 8]);
#pragma unroll
                for (int ns = 0; ns < 8; ns++) {
                    unsigned b0 = lds_u32(&Bt[ns * 8 + g][kb]);
                    unsigned b1 = lds_u32(&Bt[ns * 8 + g][kb + 8]);
                    mma16816(acc[ns][0], acc[ns][1], acc[ns][2], acc[ns][3],
                             a0, a1f, a2f, a3f, b0, b1);
                }
            }
        }
        int row0 = tile * 128 + wm + g;
#pragma unroll
        for (int ns = 0; ns < 8; ns++) {
            int col = ns * 8 + 2 * tg;
            if (row0 < NN)
                *reinterpret_cast<__half2*>(&g_h2h[(size_t)row0 * 64 + col]) =
                    __floats2half2_rn(acc[ns][0], acc[ns][1]);
            if (row0 + 8 < NN)
                *reinterpret_cast<__half2*>(&g_h2h[(size_t)(row0 + 8) * 64 + col]) =
                    __floats2half2_rn(acc[ns][2], acc[ns][3]);
        }
        float es0 = 0.f, ed0 = 0.f, es8 = 0.f, ed8 = 0.f;
#pragma unroll
        for (int ns = 0; ns < 8; ns++) {
            es0 = fmaf(acc[ns][0], alc[ns][0], fmaf(acc[ns][1], alc[ns][1], es0));
            ed0 = fmaf(acc[ns][0], arc[ns][0], fmaf(acc[ns][1], arc[ns][1], ed0));
            es8 = fmaf(acc[ns][2], alc[ns][0], fmaf(acc[ns][3], alc[ns][1], es8));
            ed8 = fmaf(acc[ns][2], arc[ns][0], fmaf(acc[ns][3], arc[ns][1], ed8));
        }
#pragma unroll
        for (int o = 1; o < 4; o <<= 1) {
            es0 += __shfl_xor_sync(0xffffffffu, es0, o);
            ed0 += __shfl_xor_sync(0xffffffffu, ed0, o);
            es8 += __shfl_xor_sync(0xffffffffu, es8, o);
            ed8 += __shfl_xor_sync(0xffffffffu, ed8, o);
        }
        if (tg == 0) {
            if (row0 < NN) {
                g_es2[row0] = es0;
                g_ed2[row0] = ed0;
                mx_es = fmaxf(mx_es, es0);
                mx_ed = fmaxf(mx_ed, ed0);
            }
            if (row0 + 8 < NN) {
                g_es2[row0 + 8] = es8;
                g_ed2[row0 + 8] = ed8;
                mx_es = fmaxf(mx_es, es8);
                mx_ed = fmaxf(mx_ed, ed8);
            }
        }
    }
#pragma unroll
    for (int o = 16; o > 0; o >>= 1) {
        mx_es = fmaxf(mx_es, __shfl_xor_sync(0xffffffffu, mx_es, o));
        mx_ed = fmaxf(mx_ed, __shfl_xor_sync(0xffffffffu, mx_ed, o));
    }
    if (lane == 0) {
        atomicMax(&g_maxes2_u, enc_f(mx_es));
        atomicMax(&g_maxed2_u, enc_f(mx_ed));
    }
}

// ---------------- layer-2 aggregation: warp/dst, unroll-2, broadcast att ----------
__global__ void __launch_bounds__(256) k_agg2(
    const float* __restrict__ user, const float* __restrict__ item) {
    int gw = (blockIdx.x * 256 + threadIdx.x) >> 5;
    int lane = threadIdx.x & 31;
    if (gw >= NN) return;
    int d = gw;
    int n0 = g_off[d];
    int cnt = g_cnt[d];
    float M = lrelu(dec_f(g_maxes2_u) + dec_f(g_maxed2_u));
    float2 acc = make_float2(0.f, 0.f);
    float ss = 0.f;
    float ed_d = g_ed2[d];
    int j = n0, end = n0 + cnt;
    for (; j + 1 < end; j += 2) {
        int s0 = g_csr_src[j];
        int s1 = g_csr_src[j + 1];
        __half2 hr0 = *reinterpret_cast<const __half2*>(&g_h2h[(size_t)s0 * 64 + lane * 2]);
        __half2 hr1 = *reinterpret_cast<const __half2*>(&g_h2h[(size_t)s1 * 64 + lane * 2]);
        float w0 = __expf(lrelu(g_es2[s0] + ed_d) - M);   // broadcast load, all lanes
        float w1 = __expf(lrelu(g_es2[s1] + ed_d) - M);
        ss += w0 + w1;
        float2 f0 = __half22float2(hr0);
        float2 f1 = __half22float2(hr1);
        acc.x = fmaf(w0, f0.x, fmaf(w1, f1.x, acc.x));
        acc.y = fmaf(w0, f0.y, fmaf(w1, f1.y, acc.y));
    }
    if (j < end) {
        int s0 = g_csr_src[j];
        __half2 hr0 = *reinterpret_cast<const __half2*>(&g_h2h[(size_t)s0 * 64 + lane * 2]);
        float w0 = __expf(lrelu(g_es2[s0] + ed_d) - M);
        ss += w0;
        float2 f0 = __half22float2(hr0);
        acc.x = fmaf(w0, f0.x, acc.x);
        acc.y = fmaf(w0, f0.y, acc.y);
    }
    float inv = 1.f / (ss + 1e-8f);
    float2 emb = (d < NUSERS)
        ? *reinterpret_cast<const float2*>(&user[(size_t)d * 64 + lane * 2])
        : *reinterpret_cast<const float2*>(&item[(size_t)(d - NUSERS) * 64 + lane * 2]);
    float2 out = make_float2(acc.x * inv + emb.x, acc.y * inv + emb.y);
    *reinterpret_cast<float2*>(&g_out2[(size_t)d * 64 + lane * 2]) = out;
}

// ---------------- final scoring -----------------------------------------------------
__global__ void k_final(const int* __restrict__ uid, const int* __restrict__ iid,
                        float* __restrict__ out) {
    int gw = (blockIdx.x * blockDim.x + threadIdx.x) >> 5;
    int lane = threadIdx.x & 31;
    if (gw >= NB) return;
    int u = uid[gw];
    int it = NUSERS + iid[gw];
    float p = 0.f;
#pragma unroll
    for (int i = 0; i < 2; i++) {
        int f = i * 32 + lane;
        p += g_out2[(size_t)u * 64 + f] * g_out2[(size_t)it * 64 + f];
    }
#pragma unroll
    for (int o = 16; o > 0; o >>= 1) p += __shfl_down_sync(0xffffffffu, p, o);
    if (lane == 0) out[gw] = p;
}

// ---------------- launch --------------------------------------------------------------
extern "C" void kernel_launch(void* const* d_in, const int* in_sizes, int n_in,
                              void* d_out, int out_size) {
    const float* user = (const float*)d_in[0];
    const float* item = (const float*)d_in[1];
    const float* W1 = (const float*)d_in[2];
    const float* a1 = (const float*)d_in[3];
    const float* W2 = (const float*)d_in[4];
    const float* a2 = (const float*)d_in[5];
    const int* ei = (const int*)d_in[6];
    const int* uid = (const int*)d_in[7];
    const int* iid = (const int*)d_in[8];
    float* out = (float*)d_out;

    k_init<<<(NN + 255) / 256, 256>>>();
    k_cvt_x<<<2048, 256>>>(user, item);
    k_cvt_w<<<64, 256>>>(W1, W2);
    k_hist<<<2048, 256>>>(ei);
    k_scan_block<<<NBLK_SCAN, 1024>>>();
    k_scan_top<<<1, 256>>>();
    k_scan_add<<<(NN + 255) / 256, 256>>>();
    k_scatter<<<(NE + 255) / 256, 256>>>(ei);
    k_gemm1_mma<<<296, 256>>>(a1);
    k_agg1<<<(NN * 32 + 255) / 256, 256>>>();
    k_gemm2_mma<<<296, 256>>>(a2);
    k_agg2<<<(NN * 32 + 255) / 256, 256>>>(user, item);
    k_final<<<NB * 32 / 256, 256>>>(uid, iid, out);
}